// round 6
// baseline (speedup 1.0000x reference)
#include <cuda_runtime.h>
#include <math.h>
#include <stdint.h>

#define BB 64
#define TT 512
#define INF 16
#define HH 512
#define JJ 8
#define NCTA 128
#define NTH 512
#define JPC 4

typedef unsigned long long ull;

// ---------------- device scratch ------------------------------------------
__device__ float g_h0t[2][HH][BB];
__device__ float g_h1t[2][HH][BB];
__device__ float g_h1seq[TT][HH][BB];      // 64 MB
__device__ float g_act[TT][BB][2*JJ];
__device__ unsigned g_barcnt, g_bargen;

// ---------------- grid barrier --------------------------------------------
__device__ __forceinline__ void gridbar()
{
    __threadfence();                 // all threads release their stores
    __syncthreads();
    if (threadIdx.x == 0) {
        unsigned g = *((volatile unsigned*)&g_bargen);
        if (atomicAdd(&g_barcnt, 1u) == NCTA - 1) {
            *((volatile unsigned*)&g_barcnt) = 0u;
            __threadfence();
            *((volatile unsigned*)&g_bargen) = g + 1u;
        } else {
            while (*((volatile unsigned*)&g_bargen) == g) {}
        }
        __threadfence();
    }
    __syncthreads();
}

__device__ __forceinline__ float sigf(float x) { return 1.f / (1.f + expf(-x)); }

__device__ __forceinline__ ull dup2(float w)
{ ull d; asm("mov.b64 %0,{%1,%1};" : "=l"(d) : "f"(w)); return d; }
__device__ __forceinline__ ull fma2(ull a, ull b, ull c)
{ ull d; asm("fma.rn.f32x2 %0,%1,%2,%3;" : "=l"(d) : "l"(a), "l"(b), "l"(c)); return d; }

__device__ __forceinline__ float gru_out(float gr, float gz, float gn,
                                         float hr, float hz, float hn, float ho)
{
    float r = sigf(gr + hr);
    float z = sigf(gz + hz);
    float n = tanhf(gn + r * hn);
    return (1.f - z) * n + z * ho;
}

// ---------------- SMEM layout (float offsets) ------------------------------
// sW2  : ull[18][512]  row-paired weights (rows: 0-11 Whh0, 12-23 Wih1, 24-35 Whh1)
// sWih0: [12][16]
// sB   : [48] bih0[12] bhh0[12] bih1[12] bhh1[12]
// sRed : ull[18*4*2*32]  partials (rp, ks, bh, lane)
#define OFF_WIH0 18432
#define OFF_B    18624
#define OFF_RED  18672
#define SMEM_FLOATS (18672 + 9216)
#define SMEM_BYTES  (SMEM_FLOATS * 4)

__global__ void __launch_bounds__(NTH, 1)
rnn_persistent(const float* __restrict__ xg,
               const float* __restrict__ Wih0, const float* __restrict__ bih0,
               const float* __restrict__ Whh0, const float* __restrict__ bhh0,
               const float* __restrict__ Wih1, const float* __restrict__ bih1,
               const float* __restrict__ Whh1, const float* __restrict__ bhh1,
               const float* __restrict__ h0in)
{
    extern __shared__ float smem[];
    ull*   sW2   = (ull*)smem;               // 9216 ull
    float* sW2f  = smem;
    float* sWih0 = smem + OFF_WIH0;
    float* sB    = smem + OFF_B;
    ull*   sRed  = (ull*)(smem + OFF_RED);   // 4608 ull
    float* sRedF = smem + OFF_RED;

    const int tid = threadIdx.x;
    const int jb  = blockIdx.x * JPC;

    // ---- build row-paired weight slab ----
    // row r: m = r/12 (0:Whh0 1:Wih1 2:Whh1), q = (r%12)/3, g = r%3
    for (int idx = tid; idx < 18 * 512; idx += NTH) {
        int rp = idx >> 9, k = idx & 511;
#pragma unroll
        for (int h = 0; h < 2; ++h) {
            int r = 2 * rp + h;
            int m = r / 12, rr = r % 12, q = rr / 3, g = rr % 3;
            const float* M = (m == 0) ? Whh0 : ((m == 1) ? Wih1 : Whh1);
            sW2f[idx * 2 + h] = M[(g * HH + jb + q) * HH + k];
        }
    }
    for (int idx = tid; idx < 12 * 16; idx += NTH) {
        int r = idx >> 4, k = idx & 15;
        int q = r / 3, g = r % 3;
        sWih0[idx] = Wih0[(g * HH + jb + q) * INF + k];
    }
    if (tid < 12) {
        int q = tid / 3, g = tid % 3;
        int grow = g * HH + jb + q;
        sB[tid]      = bih0[grow];
        sB[12 + tid] = bhh0[grow];
        sB[24 + tid] = bih1[grow];
        sB[36 + tid] = bhh1[grow];
    }

    // ---- finisher identity: one (layer, unit, batch) per thread ----
    const int fL = tid >> 8;            // 0: h0 update, 1: h1 update
    const int fq = (tid >> 6) & 3;
    const int fb = tid & 63;
    const int fbh = fb >> 5, fln = fb & 31;

    float hreg;                          // own old hidden value
    {
        hreg = h0in[(fL * BB + fb) * HH + jb + fq];
        if (fL == 0) {
            g_h0t[0][jb + fq][fb] = hreg;
        } else {
            g_h1t[0][jb + fq][fb] = hreg;
            g_h1t[1][jb + fq][fb] = hreg;   // h1[-1] for tick 1
        }
    }

    // ---- GEMM identity ----
    const int lane = tid & 31;
    const int warp = tid >> 5;          // 0..15
    const int bh   = warp & 1;
    const int ks   = (warp >> 1) & 3;
    const int rs   = warp >> 3;         // 0: rp 0-8 (all u), 1: rp 9-17 (3 u + 6 v)
    const int b    = bh * 32 + lane;
    const int k0   = ks * 128;
    const int rpb  = rs * 9;

    for (int tau = 0; tau <= TT; ++tau) {
        const int par = tau & 1;
        gridbar();

        // prefetch x for layer-0 finishers
        float4 xv0, xv1, xv2, xv3;
        if (fL == 0 && tau < TT) {
            const float4* xb4 = (const float4*)(xg + ((size_t)fb * TT + tau) * INF);
            xv0 = __ldg(xb4); xv1 = __ldg(xb4 + 1);
            xv2 = __ldg(xb4 + 2); xv3 = __ldg(xb4 + 3);
        }

        // ---- GEMM: acc[i] over 9 row-pairs, 128 k, own batch ----
        ull acc[9] = {0,0,0,0,0,0,0,0,0};
        const float* ub = &g_h0t[par][0][b];
        const float* vb = &g_h1t[par][0][b];

        if (rs == 0) {
#pragma unroll 4
            for (int kk = k0; kk < k0 + 128; kk += 4) {
                float u0 = __ldcg(ub + (kk + 0) * 64);
                float u1 = __ldcg(ub + (kk + 1) * 64);
                float u2 = __ldcg(ub + (kk + 2) * 64);
                float u3 = __ldcg(ub + (kk + 3) * 64);
                ull d0 = dup2(u0), d1 = dup2(u1), d2 = dup2(u2), d3 = dup2(u3);
#pragma unroll
                for (int i = 0; i < 9; ++i) {
                    const ulonglong2* wp = (const ulonglong2*)&sW2[(rpb + i) * 512 + kk];
                    ulonglong2 wA = wp[0], wB = wp[1];
                    acc[i] = fma2(wA.x, d0, acc[i]);
                    acc[i] = fma2(wA.y, d1, acc[i]);
                    acc[i] = fma2(wB.x, d2, acc[i]);
                    acc[i] = fma2(wB.y, d3, acc[i]);
                }
            }
        } else {
#pragma unroll 4
            for (int kk = k0; kk < k0 + 128; kk += 4) {
                float u0 = __ldcg(ub + (kk + 0) * 64);
                float u1 = __ldcg(ub + (kk + 1) * 64);
                float u2 = __ldcg(ub + (kk + 2) * 64);
                float u3 = __ldcg(ub + (kk + 3) * 64);
                float v0 = __ldcg(vb + (kk + 0) * 64);
                float v1 = __ldcg(vb + (kk + 1) * 64);
                float v2 = __ldcg(vb + (kk + 2) * 64);
                float v3 = __ldcg(vb + (kk + 3) * 64);
                ull du0 = dup2(u0), du1 = dup2(u1), du2 = dup2(u2), du3 = dup2(u3);
                ull dv0 = dup2(v0), dv1 = dup2(v1), dv2 = dup2(v2), dv3 = dup2(v3);
#pragma unroll
                for (int i = 0; i < 9; ++i) {
                    const ulonglong2* wp = (const ulonglong2*)&sW2[(rpb + i) * 512 + kk];
                    ulonglong2 wA = wp[0], wB = wp[1];
                    ull e0 = (i < 3) ? du0 : dv0, e1 = (i < 3) ? du1 : dv1;
                    ull e2 = (i < 3) ? du2 : dv2, e3 = (i < 3) ? du3 : dv3;
                    acc[i] = fma2(wA.x, e0, acc[i]);
                    acc[i] = fma2(wA.y, e1, acc[i]);
                    acc[i] = fma2(wB.x, e2, acc[i]);
                    acc[i] = fma2(wB.y, e3, acc[i]);
                }
            }
        }

#pragma unroll
        for (int i = 0; i < 9; ++i)
            sRed[(((rpb + i) * 4 + ks) * 2 + bh) * 32 + lane] = acc[i];
        __syncthreads();

        // ---- finisher: one output per thread ----
        {
            // partial sum for row r, this thread's (bh, ln)
            auto getpart = [&](int r) -> float {
                int rp = r >> 1, h = r & 1;
                float s = 0.f;
#pragma unroll
                for (int kq = 0; kq < 4; ++kq)
                    s += sRedF[((((rp * 4) + kq) * 2 + fbh) * 32 + fln) * 2 + h];
                return s;
            };

            if (fL == 0) {
                if (tau < TT) {
                    float xa[16] = {xv0.x,xv0.y,xv0.z,xv0.w, xv1.x,xv1.y,xv1.z,xv1.w,
                                    xv2.x,xv2.y,xv2.z,xv2.w, xv3.x,xv3.y,xv3.z,xv3.w};
                    float gi[3];
#pragma unroll
                    for (int g = 0; g < 3; ++g) {
                        const float* wr = sWih0 + (fq * 3 + g) * 16;
                        float s = sB[fq * 3 + g];
#pragma unroll
                        for (int k = 0; k < 16; ++k) s = fmaf(xa[k], wr[k], s);
                        gi[g] = s;
                    }
                    float Ar = getpart(fq * 3 + 0), Az = getpart(fq * 3 + 1), An = getpart(fq * 3 + 2);
                    hreg = gru_out(gi[0], gi[1], gi[2],
                                   Ar + sB[12 + fq * 3], Az + sB[13 + fq * 3],
                                   An + sB[14 + fq * 3], hreg);
                    g_h0t[par ^ 1][jb + fq][fb] = hreg;
                }
            } else {
                if (tau >= 1) {
                    float Ir = getpart(12 + fq * 3 + 0), Iz = getpart(12 + fq * 3 + 1),
                          In = getpart(12 + fq * 3 + 2);
                    float Hr = getpart(24 + fq * 3 + 0), Hz = getpart(24 + fq * 3 + 1),
                          Hn = getpart(24 + fq * 3 + 2);
                    hreg = gru_out(Ir + sB[24 + fq * 3], Iz + sB[25 + fq * 3], In + sB[26 + fq * 3],
                                   Hr + sB[36 + fq * 3], Hz + sB[37 + fq * 3], Hn + sB[38 + fq * 3],
                                   hreg);
                    g_h1t[par ^ 1][jb + fq][fb] = hreg;
                    g_h1seq[tau - 1][jb + fq][fb] = hreg;
                }
            }
        }
        __syncthreads();   // protect sRed reuse next tick
    }
}

// ---------------- batch FC head ---------------------------------------------
__global__ void __launch_bounds__(256)
fc_kernel(const float* __restrict__ fcW, const float* __restrict__ fcb)
{
    __shared__ float sW[16 * 512];
    __shared__ float sb[16];
    const int tid = threadIdx.x;
    for (int idx = tid; idx < 16 * 512; idx += 256) sW[idx] = fcW[idx];
    if (tid < 16) sb[tid] = fcb[tid];
    __syncthreads();
    const int t = blockIdx.x, b = tid & 63, og = tid >> 6;
    float a0 = sb[og*4], a1 = sb[og*4+1], a2 = sb[og*4+2], a3 = sb[og*4+3];
    const float* w0 = sW + (og*4)*512;
    const float* w1 = sW + (og*4+1)*512;
    const float* w2 = sW + (og*4+2)*512;
    const float* w3 = sW + (og*4+3)*512;
#pragma unroll 8
    for (int k = 0; k < 512; ++k) {
        float hv = g_h1seq[t][k][b];
        a0 = fmaf(hv, w0[k], a0); a1 = fmaf(hv, w1[k], a1);
        a2 = fmaf(hv, w2[k], a2); a3 = fmaf(hv, w3[k], a3);
    }
    g_act[t][b][og*4]   = sigf(a0);
    g_act[t][b][og*4+1] = sigf(a1);
    g_act[t][b][og*4+2] = sigf(a2);
    g_act[t][b][og*4+3] = sigf(a3);
}

// ---------------- physics scan ----------------------------------------------
__global__ void __launch_bounds__(BB * JJ)
physics_kernel(const float* __restrict__ theta0, const float* __restrict__ omega0,
               float* __restrict__ out)
{
    const int tid = threadIdx.x, b = tid >> 3, j = tid & 7;
    float th = theta0[b * JJ + j], om = omega0[b * JJ + j];
    const float ma0 = -0.05f, ma1 = 0.05f, dt = 1.f / 60.f;
#pragma unroll 4
    for (int t = 0; t < TT; ++t) {
        float2 a = *(const float2*)&g_act[t][b][2 * j];
        float Km0 = fmaf(2000.f, a.x, 100.f), Km1 = fmaf(2000.f, a.y, 100.f);
        float Lm0 = fmaf(0.006f, a.x, 0.06f), Lm1 = fmaf(0.006f, a.y, 0.06f);
        float F0 = Km0 * (Lm0 - ma0 * th), F1 = Km1 * (Lm1 - ma1 * th);
        float tau = ma0 * F0 + ma1 * F1;
        float acc = (tau - 5.f * th - 0.3f * om) / 0.004f;
        om = fmaf(dt, acc, om);
        th = fmaf(dt, om, th);
        out[((size_t)b * TT + t) * JJ + j] = th;
    }
}

// ---------------- launch ----------------------------------------------------
extern "C" void kernel_launch(void* const* d_in, const int* in_sizes, int n_in,
                              void* d_out, int out_size)
{
    const float* x      = (const float*)d_in[0];
    const float* W_ih0  = (const float*)d_in[1];
    const float* W_hh0  = (const float*)d_in[2];
    const float* b_ih0  = (const float*)d_in[3];
    const float* b_hh0  = (const float*)d_in[4];
    const float* W_ih1  = (const float*)d_in[5];
    const float* W_hh1  = (const float*)d_in[6];
    const float* b_ih1  = (const float*)d_in[7];
    const float* b_hh1  = (const float*)d_in[8];
    const float* fc_W   = (const float*)d_in[9];
    const float* fc_b   = (const float*)d_in[10];
    const float* h0     = (const float*)d_in[11];
    const float* theta0 = (const float*)d_in[12];
    const float* omega0 = (const float*)d_in[13];
    float* out = (float*)d_out;

    cudaFuncSetAttribute(rnn_persistent,
                         cudaFuncAttributeMaxDynamicSharedMemorySize, SMEM_BYTES);

    rnn_persistent<<<NCTA, NTH, SMEM_BYTES>>>(
        x, W_ih0, b_ih0, W_hh0, b_hh0, W_ih1, b_ih1, W_hh1, b_hh1, h0);
    fc_kernel<<<TT, 256>>>(fc_W, fc_b);
    physics_kernel<<<1, BB * JJ>>>(theta0, omega0, out);
}

// round 7
// speedup vs baseline: 1.1546x; 1.1546x over previous
#include <cuda_runtime.h>
#include <math.h>
#include <stdint.h>

#define BB 64
#define TT 512
#define INF 16
#define HH 512
#define JJ 8
#define NCTA 128
#define NTH 512
#define JPC 4

typedef unsigned long long ull;

// ---------------- device scratch ------------------------------------------
__device__ float g_h0t[2][HH][BB];
__device__ float g_h1t[2][HH][BB];
__device__ float g_h1seq[TT][HH][BB];      // 64 MB
__device__ float g_act[TT][BB][2*JJ];
__device__ unsigned g_barcnt, g_bargen;

// ---------------- grid barrier --------------------------------------------
__device__ __forceinline__ void gridbar()
{
    __threadfence();
    __syncthreads();
    if (threadIdx.x == 0) {
        unsigned g = *((volatile unsigned*)&g_bargen);
        if (atomicAdd(&g_barcnt, 1u) == NCTA - 1) {
            *((volatile unsigned*)&g_barcnt) = 0u;
            __threadfence();
            *((volatile unsigned*)&g_bargen) = g + 1u;
        } else {
            while (*((volatile unsigned*)&g_bargen) == g) {}
        }
        __threadfence();
    }
    __syncthreads();
}

__device__ __forceinline__ float sigf(float x) { return 1.f / (1.f + expf(-x)); }

__device__ __forceinline__ ull dup2(float w)
{ ull d; asm("mov.b64 %0,{%1,%1};" : "=l"(d) : "f"(w)); return d; }
__device__ __forceinline__ ull fma2(ull a, ull b, ull c)
{ ull d; asm("fma.rn.f32x2 %0,%1,%2,%3;" : "=l"(d) : "l"(a), "l"(b), "l"(c)); return d; }

__device__ __forceinline__ float gru_out(float gr, float gz, float gn,
                                         float hr, float hz, float hn, float ho)
{
    float r = sigf(gr + hr);
    float z = sigf(gz + hz);
    float n = tanhf(gn + r * hn);
    return (1.f - z) * n + z * ho;
}

// ---------------- GEMM micro-kernels ---------------------------------------
// acc[i*2+0] covers batch b=lane (rows 2rp,2rp+1 packed), acc[i*2+1] batch b+32.
template<int NRP>
__device__ __forceinline__ void gemm_one(ull* acc, const ull* __restrict__ w,
                                         const float* __restrict__ hb)
{
    float cur[16], nxt[16];
#pragma unroll
    for (int j = 0; j < 8; ++j) {
        cur[2*j]   = __ldcg(hb + j*64);
        cur[2*j+1] = __ldcg(hb + j*64 + 32);
    }
#pragma unroll 2
    for (int tile = 0; tile < 16; ++tile) {
        if (tile < 15) {
            const float* nb = hb + (tile + 1) * 8 * 64;
#pragma unroll
            for (int j = 0; j < 8; ++j) {
                nxt[2*j]   = __ldcg(nb + j*64);
                nxt[2*j+1] = __ldcg(nb + j*64 + 32);
            }
        }
#pragma unroll
        for (int s = 0; s < 4; ++s) {
            const int k = tile * 8 + 2 * s;
            ull dA0 = dup2(cur[4*s+0]), dB0 = dup2(cur[4*s+1]);
            ull dA1 = dup2(cur[4*s+2]), dB1 = dup2(cur[4*s+3]);
#pragma unroll
            for (int i = 0; i < NRP; ++i) {
                ulonglong2 wp = *(const ulonglong2*)&w[i*512 + k];
                acc[2*i]   = fma2(wp.x, dA0, acc[2*i]);
                acc[2*i+1] = fma2(wp.x, dB0, acc[2*i+1]);
                acc[2*i]   = fma2(wp.y, dA1, acc[2*i]);
                acc[2*i+1] = fma2(wp.y, dB1, acc[2*i+1]);
            }
        }
#pragma unroll
        for (int j = 0; j < 16; ++j) cur[j] = nxt[j];
    }
}

// mixed warp: rp i=0,1 use u; i=2,3 use v
__device__ __forceinline__ void gemm_mix(ull* acc, const ull* __restrict__ w,
                                         const float* __restrict__ hu,
                                         const float* __restrict__ hv)
{
    float cu[8], cv[8], nu[8], nv[8];
#pragma unroll
    for (int j = 0; j < 4; ++j) {
        cu[2*j] = __ldcg(hu + j*64); cu[2*j+1] = __ldcg(hu + j*64 + 32);
        cv[2*j] = __ldcg(hv + j*64); cv[2*j+1] = __ldcg(hv + j*64 + 32);
    }
#pragma unroll 2
    for (int tile = 0; tile < 32; ++tile) {
        if (tile < 31) {
            const float* pu = hu + (tile + 1) * 4 * 64;
            const float* pv = hv + (tile + 1) * 4 * 64;
#pragma unroll
            for (int j = 0; j < 4; ++j) {
                nu[2*j] = __ldcg(pu + j*64); nu[2*j+1] = __ldcg(pu + j*64 + 32);
                nv[2*j] = __ldcg(pv + j*64); nv[2*j+1] = __ldcg(pv + j*64 + 32);
            }
        }
#pragma unroll
        for (int s = 0; s < 2; ++s) {
            const int k = tile * 4 + 2 * s;
            ull uA0 = dup2(cu[4*s+0]), uB0 = dup2(cu[4*s+1]);
            ull uA1 = dup2(cu[4*s+2]), uB1 = dup2(cu[4*s+3]);
            ull vA0 = dup2(cv[4*s+0]), vB0 = dup2(cv[4*s+1]);
            ull vA1 = dup2(cv[4*s+2]), vB1 = dup2(cv[4*s+3]);
#pragma unroll
            for (int i = 0; i < 2; ++i) {
                ulonglong2 wp = *(const ulonglong2*)&w[i*512 + k];
                acc[2*i]   = fma2(wp.x, uA0, acc[2*i]);
                acc[2*i+1] = fma2(wp.x, uB0, acc[2*i+1]);
                acc[2*i]   = fma2(wp.y, uA1, acc[2*i]);
                acc[2*i+1] = fma2(wp.y, uB1, acc[2*i+1]);
            }
#pragma unroll
            for (int i = 2; i < 4; ++i) {
                ulonglong2 wp = *(const ulonglong2*)&w[i*512 + k];
                acc[2*i]   = fma2(wp.x, vA0, acc[2*i]);
                acc[2*i+1] = fma2(wp.x, vB0, acc[2*i+1]);
                acc[2*i]   = fma2(wp.y, vA1, acc[2*i]);
                acc[2*i+1] = fma2(wp.y, vB1, acc[2*i+1]);
            }
        }
#pragma unroll
        for (int j = 0; j < 8; ++j) { cu[j] = nu[j]; cv[j] = nv[j]; }
    }
}

// ---------------- SMEM layout (float offsets) ------------------------------
#define OFF_WIH0 18432
#define OFF_B    18624
#define OFF_RED  18672
#define SMEM_FLOATS (18672 + 9216)
#define SMEM_BYTES  (SMEM_FLOATS * 4)

__global__ void __launch_bounds__(NTH, 1)
rnn_persistent(const float* __restrict__ xg,
               const float* __restrict__ Wih0, const float* __restrict__ bih0,
               const float* __restrict__ Whh0, const float* __restrict__ bhh0,
               const float* __restrict__ Wih1, const float* __restrict__ bih1,
               const float* __restrict__ Whh1, const float* __restrict__ bhh1,
               const float* __restrict__ h0in)
{
    extern __shared__ float smem[];
    ull*   sW2   = (ull*)smem;               // 9216 ull row-paired weights
    float* sW2f  = smem;
    float* sWih0 = smem + OFF_WIH0;
    float* sB    = smem + OFF_B;
    ull*   sRed  = (ull*)(smem + OFF_RED);
    float* sRedF = smem + OFF_RED;

    const int tid = threadIdx.x;
    const int jb  = blockIdx.x * JPC;

    // ---- row-paired weight slab: rows 0-11 Whh0, 12-23 Wih1, 24-35 Whh1 ----
    for (int idx = tid; idx < 18 * 512; idx += NTH) {
        int rp = idx >> 9, k = idx & 511;
#pragma unroll
        for (int h = 0; h < 2; ++h) {
            int r = 2 * rp + h;
            int m = r / 12, rr = r % 12, q = rr / 3, g = rr % 3;
            const float* M = (m == 0) ? Whh0 : ((m == 1) ? Wih1 : Whh1);
            sW2f[idx * 2 + h] = M[(g * HH + jb + q) * HH + k];
        }
    }
    for (int idx = tid; idx < 12 * 16; idx += NTH) {
        int r = idx >> 4, k = idx & 15;
        int q = r / 3, g = r % 3;
        sWih0[idx] = Wih0[(g * HH + jb + q) * INF + k];
    }
    if (tid < 12) {
        int q = tid / 3, g = tid % 3;
        int grow = g * HH + jb + q;
        sB[tid]      = bih0[grow];
        sB[12 + tid] = bhh0[grow];
        sB[24 + tid] = bih1[grow];
        sB[36 + tid] = bhh1[grow];
    }

    // ---- finisher identity ----
    const int fL = tid >> 8;
    const int fq = (tid >> 6) & 3;
    const int fb = tid & 63;
    const int fbh = fb >> 5, fln = fb & 31;

    float hreg = h0in[(fL * BB + fb) * HH + jb + fq];
    if (fL == 0) {
        g_h0t[0][jb + fq][fb] = hreg;
    } else {
        g_h1t[0][jb + fq][fb] = hreg;
        g_h1t[1][jb + fq][fb] = hreg;   // h1[-1] for tick 1
    }

    // ---- GEMM identity: 16 warps = ks(4) x rs(4) ----
    const int lane = tid & 31;
    const int warp = tid >> 5;
    const int ks   = warp >> 2;         // k-slice (128 k)
    const int rs   = warp & 3;          // row-pair group
    const int k0   = ks * 128;

    for (int tau = 0; tau <= TT; ++tau) {
        const int par = tau & 1;
        gridbar();

        // prefetch x for layer-0 finishers
        float4 xv0, xv1, xv2, xv3;
        if (fL == 0 && tau < TT) {
            const float4* xb4 = (const float4*)(xg + ((size_t)fb * TT + tau) * INF);
            xv0 = __ldg(xb4); xv1 = __ldg(xb4 + 1);
            xv2 = __ldg(xb4 + 2); xv3 = __ldg(xb4 + 3);
        }

        const float* ub = &g_h0t[par][k0][lane];
        const float* vb = &g_h1t[par][k0][lane];

        ull acc[10];
#pragma unroll
        for (int i = 0; i < 10; ++i) acc[i] = 0ull;

        if (rs == 0) {                 // rp 0-4 (u)
            gemm_one<5>(acc, sW2 + 0 * 512 + k0, ub);
#pragma unroll
            for (int i = 0; i < 5; ++i) {
                sRed[(((0 + i) * 4 + ks) * 2 + 0) * 32 + lane] = acc[2*i];
                sRed[(((0 + i) * 4 + ks) * 2 + 1) * 32 + lane] = acc[2*i+1];
            }
        } else if (rs == 1) {          // rp 5-9 (u)
            gemm_one<5>(acc, sW2 + 5 * 512 + k0, ub);
#pragma unroll
            for (int i = 0; i < 5; ++i) {
                sRed[(((5 + i) * 4 + ks) * 2 + 0) * 32 + lane] = acc[2*i];
                sRed[(((5 + i) * 4 + ks) * 2 + 1) * 32 + lane] = acc[2*i+1];
            }
        } else if (rs == 2) {          // rp 10,11 (u) + rp 12,13 (v)
            gemm_mix(acc, sW2 + 10 * 512 + k0, ub, vb);
#pragma unroll
            for (int i = 0; i < 4; ++i) {
                sRed[(((10 + i) * 4 + ks) * 2 + 0) * 32 + lane] = acc[2*i];
                sRed[(((10 + i) * 4 + ks) * 2 + 1) * 32 + lane] = acc[2*i+1];
            }
        } else {                       // rp 14-17 (v)
            gemm_one<4>(acc, sW2 + 14 * 512 + k0, vb);
#pragma unroll
            for (int i = 0; i < 4; ++i) {
                sRed[(((14 + i) * 4 + ks) * 2 + 0) * 32 + lane] = acc[2*i];
                sRed[(((14 + i) * 4 + ks) * 2 + 1) * 32 + lane] = acc[2*i+1];
            }
        }
        __syncthreads();

        // ---- finisher: one output per thread ----
        {
            auto getpart = [&](int r) -> float {
                int rp = r >> 1, h = r & 1;
                float s = 0.f;
#pragma unroll
                for (int kq = 0; kq < 4; ++kq)
                    s += sRedF[((((rp * 4) + kq) * 2 + fbh) * 32 + fln) * 2 + h];
                return s;
            };

            if (fL == 0) {
                if (tau < TT) {
                    float xa[16] = {xv0.x,xv0.y,xv0.z,xv0.w, xv1.x,xv1.y,xv1.z,xv1.w,
                                    xv2.x,xv2.y,xv2.z,xv2.w, xv3.x,xv3.y,xv3.z,xv3.w};
                    float gi[3];
#pragma unroll
                    for (int g = 0; g < 3; ++g) {
                        const float* wr = sWih0 + (fq * 3 + g) * 16;
                        float s = sB[fq * 3 + g];
#pragma unroll
                        for (int k = 0; k < 16; ++k) s = fmaf(xa[k], wr[k], s);
                        gi[g] = s;
                    }
                    float Ar = getpart(fq * 3 + 0), Az = getpart(fq * 3 + 1),
                          An = getpart(fq * 3 + 2);
                    hreg = gru_out(gi[0], gi[1], gi[2],
                                   Ar + sB[12 + fq * 3], Az + sB[13 + fq * 3],
                                   An + sB[14 + fq * 3], hreg);
                    g_h0t[par ^ 1][jb + fq][fb] = hreg;
                }
            } else {
                if (tau >= 1) {
                    float Ir = getpart(12 + fq * 3 + 0), Iz = getpart(12 + fq * 3 + 1),
                          In = getpart(12 + fq * 3 + 2);
                    float Hr = getpart(24 + fq * 3 + 0), Hz = getpart(24 + fq * 3 + 1),
                          Hn = getpart(24 + fq * 3 + 2);
                    hreg = gru_out(Ir + sB[24 + fq * 3], Iz + sB[25 + fq * 3], In + sB[26 + fq * 3],
                                   Hr + sB[36 + fq * 3], Hz + sB[37 + fq * 3], Hn + sB[38 + fq * 3],
                                   hreg);
                    g_h1t[par ^ 1][jb + fq][fb] = hreg;
                    g_h1seq[tau - 1][jb + fq][fb] = hreg;
                }
            }
        }
        __syncthreads();   // protect sRed reuse next tick
    }
}

// ---------------- batch FC head ---------------------------------------------
__global__ void __launch_bounds__(256)
fc_kernel(const float* __restrict__ fcW, const float* __restrict__ fcb)
{
    __shared__ float sW[16 * 512];
    __shared__ float sb[16];
    const int tid = threadIdx.x;
    for (int idx = tid; idx < 16 * 512; idx += 256) sW[idx] = fcW[idx];
    if (tid < 16) sb[tid] = fcb[tid];
    __syncthreads();
    const int t = blockIdx.x, b = tid & 63, og = tid >> 6;
    float a0 = sb[og*4], a1 = sb[og*4+1], a2 = sb[og*4+2], a3 = sb[og*4+3];
    const float* w0 = sW + (og*4)*512;
    const float* w1 = sW + (og*4+1)*512;
    const float* w2 = sW + (og*4+2)*512;
    const float* w3 = sW + (og*4+3)*512;
#pragma unroll 8
    for (int k = 0; k < 512; ++k) {
        float hv = g_h1seq[t][k][b];
        a0 = fmaf(hv, w0[k], a0); a1 = fmaf(hv, w1[k], a1);
        a2 = fmaf(hv, w2[k], a2); a3 = fmaf(hv, w3[k], a3);
    }
    g_act[t][b][og*4]   = sigf(a0);
    g_act[t][b][og*4+1] = sigf(a1);
    g_act[t][b][og*4+2] = sigf(a2);
    g_act[t][b][og*4+3] = sigf(a3);
}

// ---------------- physics scan ----------------------------------------------
__global__ void __launch_bounds__(BB * JJ)
physics_kernel(const float* __restrict__ theta0, const float* __restrict__ omega0,
               float* __restrict__ out)
{
    const int tid = threadIdx.x, b = tid >> 3, j = tid & 7;
    float th = theta0[b * JJ + j], om = omega0[b * JJ + j];
    const float ma0 = -0.05f, ma1 = 0.05f, dt = 1.f / 60.f;
#pragma unroll 4
    for (int t = 0; t < TT; ++t) {
        float2 a = *(const float2*)&g_act[t][b][2 * j];
        float Km0 = fmaf(2000.f, a.x, 100.f), Km1 = fmaf(2000.f, a.y, 100.f);
        float Lm0 = fmaf(0.006f, a.x, 0.06f), Lm1 = fmaf(0.006f, a.y, 0.06f);
        float F0 = Km0 * (Lm0 - ma0 * th), F1 = Km1 * (Lm1 - ma1 * th);
        float tau = ma0 * F0 + ma1 * F1;
        float acc = (tau - 5.f * th - 0.3f * om) / 0.004f;
        om = fmaf(dt, acc, om);
        th = fmaf(dt, om, th);
        out[((size_t)b * TT + t) * JJ + j] = th;
    }
}

// ---------------- launch ----------------------------------------------------
extern "C" void kernel_launch(void* const* d_in, const int* in_sizes, int n_in,
                              void* d_out, int out_size)
{
    const float* x      = (const float*)d_in[0];
    const float* W_ih0  = (const float*)d_in[1];
    const float* W_hh0  = (const float*)d_in[2];
    const float* b_ih0  = (const float*)d_in[3];
    const float* b_hh0  = (const float*)d_in[4];
    const float* W_ih1  = (const float*)d_in[5];
    const float* W_hh1  = (const float*)d_in[6];
    const float* b_ih1  = (const float*)d_in[7];
    const float* b_hh1  = (const float*)d_in[8];
    const float* fc_W   = (const float*)d_in[9];
    const float* fc_b   = (const float*)d_in[10];
    const float* h0     = (const float*)d_in[11];
    const float* theta0 = (const float*)d_in[12];
    const float* omega0 = (const float*)d_in[13];
    float* out = (float*)d_out;

    cudaFuncSetAttribute(rnn_persistent,
                         cudaFuncAttributeMaxDynamicSharedMemorySize, SMEM_BYTES);

    rnn_persistent<<<NCTA, NTH, SMEM_BYTES>>>(
        x, W_ih0, b_ih0, W_hh0, b_hh0, W_ih1, b_ih1, W_hh1, b_hh1, h0);
    fc_kernel<<<TT, 256>>>(fc_W, fc_b);
    physics_kernel<<<1, BB * JJ>>>(theta0, omega0, out);
}

// round 9
// speedup vs baseline: 1.2059x; 1.0444x over previous
#include <cuda_runtime.h>
#include <math.h>
#include <stdint.h>

#define BB 64
#define TT 512
#define INF 16
#define HH 512
#define JJ 8
#define NCTA 128
#define NTH 768
#define JPC 4

typedef unsigned long long ull;

// ---------------- device scratch ------------------------------------------
__device__ float g_h0t[2][HH][BB];
__device__ float g_h1t[2][HH][BB];
__device__ float g_h1seq[TT][HH][BB];      // 64 MB
__device__ float g_act[TT][BB][2*JJ];
__device__ unsigned g_barcnt, g_bargen;

// ---------------- grid barrier --------------------------------------------
__device__ __forceinline__ void gridbar()
{
    __threadfence();
    __syncthreads();
    if (threadIdx.x == 0) {
        unsigned g = *((volatile unsigned*)&g_bargen);
        if (atomicAdd(&g_barcnt, 1u) == NCTA - 1) {
            *((volatile unsigned*)&g_barcnt) = 0u;
            __threadfence();
            *((volatile unsigned*)&g_bargen) = g + 1u;
        } else {
            while (*((volatile unsigned*)&g_bargen) == g) {}
        }
        __threadfence();
    }
    __syncthreads();
}

__device__ __forceinline__ float sigf(float x) { return 1.f / (1.f + expf(-x)); }

__device__ __forceinline__ ull dup2(float w)
{ ull d; asm("mov.b64 %0,{%1,%1};" : "=l"(d) : "f"(w)); return d; }
__device__ __forceinline__ ull fma2(ull a, ull b, ull c)
{ ull d; asm("fma.rn.f32x2 %0,%1,%2,%3;" : "=l"(d) : "l"(a), "l"(b), "l"(c)); return d; }

__device__ __forceinline__ float gru_out(float gr, float gz, float gn,
                                         float hr, float hz, float hn, float ho)
{
    float r = sigf(gr + hr);
    float z = sigf(gz + hz);
    float n = tanhf(gn + r * hn);
    return (1.f - z) * n + z * ho;
}

// ---------------- GEMM micro-kernel: 3 row-pairs x 128 k x 2 batches --------
// acc[2i] = batch b=lane (rows 2rp,2rp+1 packed), acc[2i+1] = batch b+32.
__device__ __forceinline__ void gemm3(ull* acc, const ull* __restrict__ w,
                                      const float* __restrict__ hb)
{
    float cur[8], nxt[8];
#pragma unroll
    for (int j = 0; j < 4; ++j) {
        cur[2*j]   = __ldcg(hb + j*64);
        cur[2*j+1] = __ldcg(hb + j*64 + 32);
    }
#pragma unroll 4
    for (int tile = 0; tile < 32; ++tile) {
        if (tile < 31) {
            const float* nb = hb + (tile + 1) * 4 * 64;
#pragma unroll
            for (int j = 0; j < 4; ++j) {
                nxt[2*j]   = __ldcg(nb + j*64);
                nxt[2*j+1] = __ldcg(nb + j*64 + 32);
            }
        }
#pragma unroll
        for (int s = 0; s < 2; ++s) {
            const int k = tile * 4 + 2 * s;
            ull dA0 = dup2(cur[4*s+0]), dB0 = dup2(cur[4*s+1]);
            ull dA1 = dup2(cur[4*s+2]), dB1 = dup2(cur[4*s+3]);
#pragma unroll
            for (int i = 0; i < 3; ++i) {
                ulonglong2 wp = *(const ulonglong2*)&w[i*512 + k];
                acc[2*i]   = fma2(wp.x, dA0, acc[2*i]);
                acc[2*i+1] = fma2(wp.x, dB0, acc[2*i+1]);
                acc[2*i]   = fma2(wp.y, dA1, acc[2*i]);
                acc[2*i+1] = fma2(wp.y, dB1, acc[2*i+1]);
            }
        }
#pragma unroll
        for (int j = 0; j < 8; ++j) cur[j] = nxt[j];
    }
}

// ---------------- SMEM layout (float offsets) ------------------------------
#define OFF_WIH0 18432
#define OFF_B    18624
#define OFF_RED  18672
#define SMEM_FLOATS (18672 + 9216)
#define SMEM_BYTES  (SMEM_FLOATS * 4)

__global__ void __launch_bounds__(NTH, 1)
rnn_persistent(const float* __restrict__ xg,
               const float* __restrict__ Wih0, const float* __restrict__ bih0,
               const float* __restrict__ Whh0, const float* __restrict__ bhh0,
               const float* __restrict__ Wih1, const float* __restrict__ bih1,
               const float* __restrict__ Whh1, const float* __restrict__ bhh1,
               const float* __restrict__ h0in)
{
    extern __shared__ float smem[];
    ull*   sW2   = (ull*)smem;               // 9216 ull row-paired weights
    float* sW2f  = smem;
    float* sWih0 = smem + OFF_WIH0;
    float* sB    = smem + OFF_B;
    ull*   sRed  = (ull*)(smem + OFF_RED);
    float* sRedF = smem + OFF_RED;

    const int tid = threadIdx.x;
    const int jb  = blockIdx.x * JPC;

    // ---- row-paired weight slab: rows 0-11 Whh0, 12-23 Wih1, 24-35 Whh1 ----
    for (int idx = tid; idx < 18 * 512; idx += NTH) {
        int rp = idx >> 9, k = idx & 511;
#pragma unroll
        for (int h = 0; h < 2; ++h) {
            int r = 2 * rp + h;
            int m = r / 12, rr = r % 12, q = rr / 3, g = rr % 3;
            const float* M = (m == 0) ? Whh0 : ((m == 1) ? Wih1 : Whh1);
            sW2f[idx * 2 + h] = M[(g * HH + jb + q) * HH + k];
        }
    }
    for (int idx = tid; idx < 12 * 16; idx += NTH) {
        int r = idx >> 4, k = idx & 15;
        int q = r / 3, g = r % 3;
        sWih0[idx] = Wih0[(g * HH + jb + q) * INF + k];
    }
    if (tid < 12) {
        int q = tid / 3, g = tid % 3;
        int grow = g * HH + jb + q;
        sB[tid]      = bih0[grow];
        sB[12 + tid] = bhh0[grow];
        sB[24 + tid] = bih1[grow];
        sB[36 + tid] = bhh1[grow];
    }

    // ---- finisher identity (threads 0-511) ----
    const int fL = (tid >> 8) & 1;
    const int fq = (tid >> 6) & 3;
    const int fb = tid & 63;
    const int fbh = fb >> 5, fln = fb & 31;

    float hreg = 0.f;
    if (tid < 512) {
        hreg = h0in[(fL * BB + fb) * HH + jb + fq];
        if (fL == 0) {
            g_h0t[0][jb + fq][fb] = hreg;
        } else {
            g_h1t[0][jb + fq][fb] = hreg;
            g_h1t[1][jb + fq][fb] = hreg;   // h1[-1] for tick 1
        }
    }

    // ---- GEMM identity: 24 warps = ks(4) x rs(6) ----
    const int lane = tid & 31;
    const int warp = tid >> 5;
    const int rs   = warp % 6;          // row-pair group (3 rp each)
    const int ks   = warp / 6;          // k-slice (128 k)
    const int rpb  = rs * 3;
    const int k0   = ks * 128;

    for (int tau = 0; tau <= TT; ++tau) {
        const int par = tau & 1;
        gridbar();

        // ---- GEMM ----
        const float* hb = (rs < 4) ? &g_h0t[par][k0][lane] : &g_h1t[par][k0][lane];
        ull acc[6] = {0, 0, 0, 0, 0, 0};
        gemm3(acc, sW2 + rpb * 512 + k0, hb);

#pragma unroll
        for (int i = 0; i < 3; ++i) {
            sRed[(((rpb + i) * 4 + ks) * 2 + 0) * 32 + lane] = acc[2*i];
            sRed[(((rpb + i) * 4 + ks) * 2 + 1) * 32 + lane] = acc[2*i+1];
        }
        __syncthreads();

        // ---- finisher: one output per thread (threads 0-511) ----
        if (tid < 512) {
            auto getpart = [&](int r) -> float {
                int rp = r >> 1, h = r & 1;
                float s = 0.f;
#pragma unroll
                for (int kq = 0; kq < 4; ++kq)
                    s += sRedF[((((rp * 4) + kq) * 2 + fbh) * 32 + fln) * 2 + h];
                return s;
            };

            if (fL == 0) {
                if (tau < TT) {
                    const float4* xb4 = (const float4*)(xg + ((size_t)fb * TT + tau) * INF);
                    float4 xv0 = __ldg(xb4), xv1 = __ldg(xb4 + 1);
                    float4 xv2 = __ldg(xb4 + 2), xv3 = __ldg(xb4 + 3);
                    float xa[16] = {xv0.x,xv0.y,xv0.z,xv0.w, xv1.x,xv1.y,xv1.z,xv1.w,
                                    xv2.x,xv2.y,xv2.z,xv2.w, xv3.x,xv3.y,xv3.z,xv3.w};
                    float gi[3];
#pragma unroll
                    for (int g = 0; g < 3; ++g) {
                        const float* wr = sWih0 + (fq * 3 + g) * 16;
                        float s = sB[fq * 3 + g];
#pragma unroll
                        for (int k = 0; k < 16; ++k) s = fmaf(xa[k], wr[k], s);
                        gi[g] = s;
                    }
                    float Ar = getpart(fq * 3 + 0), Az = getpart(fq * 3 + 1),
                          An = getpart(fq * 3 + 2);
                    hreg = gru_out(gi[0], gi[1], gi[2],
                                   Ar + sB[12 + fq * 3], Az + sB[13 + fq * 3],
                                   An + sB[14 + fq * 3], hreg);
                    g_h0t[par ^ 1][jb + fq][fb] = hreg;
                }
            } else {
                if (tau >= 1) {
                    float Ir = getpart(12 + fq * 3 + 0), Iz = getpart(12 + fq * 3 + 1),
                          In = getpart(12 + fq * 3 + 2);
                    float Hr = getpart(24 + fq * 3 + 0), Hz = getpart(24 + fq * 3 + 1),
                          Hn = getpart(24 + fq * 3 + 2);
                    hreg = gru_out(Ir + sB[24 + fq * 3], Iz + sB[25 + fq * 3], In + sB[26 + fq * 3],
                                   Hr + sB[36 + fq * 3], Hz + sB[37 + fq * 3], Hn + sB[38 + fq * 3],
                                   hreg);
                    g_h1t[par ^ 1][jb + fq][fb] = hreg;
                    g_h1seq[tau - 1][jb + fq][fb] = hreg;
                }
            }
        }
        // NOTE: no trailing __syncthreads — next tick's gridbar orders sRed reuse.
    }
}

// ---------------- batch FC head ---------------------------------------------
__global__ void __launch_bounds__(256)
fc_kernel(const float* __restrict__ fcW, const float* __restrict__ fcb)
{
    __shared__ float sW[16 * 512];
    __shared__ float sb[16];
    const int tid = threadIdx.x;
    for (int idx = tid; idx < 16 * 512; idx += 256) sW[idx] = fcW[idx];
    if (tid < 16) sb[tid] = fcb[tid];
    __syncthreads();
    const int t = blockIdx.x, b = tid & 63, og = tid >> 6;
    float a0 = sb[og*4], a1 = sb[og*4+1], a2 = sb[og*4+2], a3 = sb[og*4+3];
    const float* w0 = sW + (og*4)*512;
    const float* w1 = sW + (og*4+1)*512;
    const float* w2 = sW + (og*4+2)*512;
    const float* w3 = sW + (og*4+3)*512;
#pragma unroll 8
    for (int k = 0; k < 512; ++k) {
        float hv = g_h1seq[t][k][b];
        a0 = fmaf(hv, w0[k], a0); a1 = fmaf(hv, w1[k], a1);
        a2 = fmaf(hv, w2[k], a2); a3 = fmaf(hv, w3[k], a3);
    }
    g_act[t][b][og*4]   = sigf(a0);
    g_act[t][b][og*4+1] = sigf(a1);
    g_act[t][b][og*4+2] = sigf(a2);
    g_act[t][b][og*4+3] = sigf(a3);
}

// ---------------- physics scan ----------------------------------------------
__global__ void __launch_bounds__(BB * JJ)
physics_kernel(const float* __restrict__ theta0, const float* __restrict__ omega0,
               float* __restrict__ out)
{
    const int tid = threadIdx.x, b = tid >> 3, j = tid & 7;
    float th = theta0[b * JJ + j], om = omega0[b * JJ + j];
    const float ma0 = -0.05f, ma1 = 0.05f, dt = 1.f / 60.f;
#pragma unroll 4
    for (int t = 0; t < TT; ++t) {
        float2 a = *(const float2*)&g_act[t][b][2 * j];
        float Km0 = fmaf(2000.f, a.x, 100.f), Km1 = fmaf(2000.f, a.y, 100.f);
        float Lm0 = fmaf(0.006f, a.x, 0.06f), Lm1 = fmaf(0.006f, a.y, 0.06f);
        float F0 = Km0 * (Lm0 - ma0 * th), F1 = Km1 * (Lm1 - ma1 * th);
        float tau = ma0 * F0 + ma1 * F1;
        float acc = (tau - 5.f * th - 0.3f * om) / 0.004f;
        om = fmaf(dt, acc, om);
        th = fmaf(dt, om, th);
        out[((size_t)b * TT + t) * JJ + j] = th;
    }
}

// ---------------- launch ----------------------------------------------------
extern "C" void kernel_launch(void* const* d_in, const int* in_sizes, int n_in,
                              void* d_out, int out_size)
{
    const float* x      = (const float*)d_in[0];
    const float* W_ih0  = (const float*)d_in[1];
    const float* W_hh0  = (const float*)d_in[2];
    const float* b_ih0  = (const float*)d_in[3];
    const float* b_hh0  = (const float*)d_in[4];
    const float* W_ih1  = (const float*)d_in[5];
    const float* W_hh1  = (const float*)d_in[6];
    const float* b_ih1  = (const float*)d_in[7];
    const float* b_hh1  = (const float*)d_in[8];
    const float* fc_W   = (const float*)d_in[9];
    const float* fc_b   = (const float*)d_in[10];
    const float* h0     = (const float*)d_in[11];
    const float* theta0 = (const float*)d_in[12];
    const float* omega0 = (const float*)d_in[13];
    float* out = (float*)d_out;

    cudaFuncSetAttribute(rnn_persistent,
                         cudaFuncAttributeMaxDynamicSharedMemorySize, SMEM_BYTES);

    rnn_persistent<<<NCTA, NTH, SMEM_BYTES>>>(
        x, W_ih0, b_ih0, W_hh0, b_hh0, W_ih1, b_ih1, W_hh1, b_hh1, h0);
    fc_kernel<<<TT, 256>>>(fc_W, fc_b);
    physics_kernel<<<1, BB * JJ>>>(theta0, omega0, out);
}

// round 10
// speedup vs baseline: 1.3250x; 1.0988x over previous
#include <cuda_runtime.h>
#include <math.h>
#include <stdint.h>

#define BB 64
#define TT 512
#define INF 16
#define HH 512
#define JJ 8
#define NCTA 128
#define NTH 768
#define JPC 4

typedef unsigned long long ull;

// ---------------- device scratch ------------------------------------------
__device__ float g_h0t[2][HH][BB];
__device__ float g_h1t[2][HH][BB];
__device__ float g_h1seq[TT][HH][BB];      // 64 MB
__device__ float g_act[TT][BB][2*JJ];
__device__ unsigned g_barcnt, g_bargen;

// ---------------- grid barrier --------------------------------------------
__device__ __forceinline__ void gridbar()
{
    __threadfence();
    __syncthreads();
    if (threadIdx.x == 0) {
        unsigned g = *((volatile unsigned*)&g_bargen);
        if (atomicAdd(&g_barcnt, 1u) == NCTA - 1) {
            *((volatile unsigned*)&g_barcnt) = 0u;
            __threadfence();
            *((volatile unsigned*)&g_bargen) = g + 1u;
        } else {
            while (*((volatile unsigned*)&g_bargen) == g) {}
        }
        __threadfence();
    }
    __syncthreads();
}

__device__ __forceinline__ float sigf(float x) { return 1.f / (1.f + expf(-x)); }

__device__ __forceinline__ ull dup2(float w)
{ ull d; asm("mov.b64 %0,{%1,%1};" : "=l"(d) : "f"(w)); return d; }
__device__ __forceinline__ ull fma2(ull a, ull b, ull c)
{ ull d; asm("fma.rn.f32x2 %0,%1,%2,%3;" : "=l"(d) : "l"(a), "l"(b), "l"(c)); return d; }

__device__ __forceinline__ float gru_out(float gr, float gz, float gn,
                                         float hr, float hz, float hn, float ho)
{
    float r = sigf(gr + hr);
    float z = sigf(gz + hz);
    float n = tanhf(gn + r * hn);
    return (1.f - z) * n + z * ho;
}

// ---------------- GEMM micro-kernel: 6 row-pairs x 64 k x 2 batches ---------
// acc[2i] = batch b=lane (rows 2rp,2rp+1 packed), acc[2i+1] = batch b+32.
// 16 tiles of 4 k; LDG prefetch 2 tiles deep.
__device__ __forceinline__ void gemm6(ull* acc, const ull* __restrict__ w,
                                      const float* __restrict__ hb)
{
    float buf[3][8];
#pragma unroll
    for (int j = 0; j < 4; ++j) {
        buf[0][2*j]   = __ldcg(hb + j*64);
        buf[0][2*j+1] = __ldcg(hb + j*64 + 32);
        buf[1][2*j]   = __ldcg(hb + (4+j)*64);
        buf[1][2*j+1] = __ldcg(hb + (4+j)*64 + 32);
    }
#pragma unroll
    for (int tile = 0; tile < 16; ++tile) {
        if (tile < 14) {
            const float* nb = hb + (tile + 2) * 4 * 64;
            float* dst = buf[(tile + 2) % 3];
#pragma unroll
            for (int j = 0; j < 4; ++j) {
                dst[2*j]   = __ldcg(nb + j*64);
                dst[2*j+1] = __ldcg(nb + j*64 + 32);
            }
        }
        const float* cb = buf[tile % 3];
#pragma unroll
        for (int s = 0; s < 2; ++s) {
            const int kk = tile * 4 + 2 * s;
            ull dA0 = dup2(cb[4*s+0]), dB0 = dup2(cb[4*s+1]);
            ull dA1 = dup2(cb[4*s+2]), dB1 = dup2(cb[4*s+3]);
#pragma unroll
            for (int i = 0; i < 6; ++i) {
                ulonglong2 wp = *(const ulonglong2*)&w[i*512 + kk];
                acc[2*i]   = fma2(wp.x, dA0, acc[2*i]);
                acc[2*i+1] = fma2(wp.x, dB0, acc[2*i+1]);
                acc[2*i]   = fma2(wp.y, dA1, acc[2*i]);
                acc[2*i+1] = fma2(wp.y, dB1, acc[2*i+1]);
            }
        }
    }
}

// ---------------- SMEM layout (float offsets) ------------------------------
// sW2[18*512] ull | sWih0[12*16] | sB[48] | sRed[18 rp][8 kq][2 bh][32] ull
#define OFF_WIH0 18432
#define OFF_B    18624
#define OFF_RED  18672
#define SMEM_FLOATS (18672 + 18432)
#define SMEM_BYTES  (SMEM_FLOATS * 4)

__global__ void __launch_bounds__(NTH, 1)
rnn_persistent(const float* __restrict__ xg,
               const float* __restrict__ Wih0, const float* __restrict__ bih0,
               const float* __restrict__ Whh0, const float* __restrict__ bhh0,
               const float* __restrict__ Wih1, const float* __restrict__ bih1,
               const float* __restrict__ Whh1, const float* __restrict__ bhh1,
               const float* __restrict__ h0in)
{
    extern __shared__ float smem[];
    ull*   sW2   = (ull*)smem;               // 9216 ull row-paired weights
    float* sW2f  = smem;
    float* sWih0 = smem + OFF_WIH0;
    float* sB    = smem + OFF_B;
    ull*   sRed  = (ull*)(smem + OFF_RED);
    float* sRedF = smem + OFF_RED;

    const int tid = threadIdx.x;
    const int jb  = blockIdx.x * JPC;

    // ---- row-paired weight slab: rows 0-11 Whh0, 12-23 Wih1, 24-35 Whh1 ----
    for (int idx = tid; idx < 18 * 512; idx += NTH) {
        int rp = idx >> 9, k = idx & 511;
#pragma unroll
        for (int h = 0; h < 2; ++h) {
            int r = 2 * rp + h;
            int m = r / 12, rr = r % 12, q = rr / 3, g = rr % 3;
            const float* M = (m == 0) ? Whh0 : ((m == 1) ? Wih1 : Whh1);
            sW2f[idx * 2 + h] = M[(g * HH + jb + q) * HH + k];
        }
    }
    for (int idx = tid; idx < 12 * 16; idx += NTH) {
        int r = idx >> 4, k = idx & 15;
        int q = r / 3, g = r % 3;
        sWih0[idx] = Wih0[(g * HH + jb + q) * INF + k];
    }
    if (tid < 12) {
        int q = tid / 3, g = tid % 3;
        int grow = g * HH + jb + q;
        sB[tid]      = bih0[grow];
        sB[12 + tid] = bhh0[grow];
        sB[24 + tid] = bih1[grow];
        sB[36 + tid] = bhh1[grow];
    }

    // ---- finisher identity (threads 0-511) ----
    const int fL = (tid >> 8) & 1;
    const int fq = (tid >> 6) & 3;
    const int fb = tid & 63;
    const int fbh = fb >> 5, fln = fb & 31;

    float hreg = 0.f;
    if (tid < 512) {
        hreg = h0in[(fL * BB + fb) * HH + jb + fq];
        if (fL == 0) {
            g_h0t[0][jb + fq][fb] = hreg;
        } else {
            g_h1t[0][jb + fq][fb] = hreg;
            g_h1t[1][jb + fq][fb] = hreg;   // h1[-1] for tick 1
        }
    }

    // ---- GEMM identity: 24 warps = 16 u-warps (8 ks x 2 rs) + 8 v-warps ----
    const int lane = tid & 31;
    const int warp = tid >> 5;
    int ks, rpb, isU;
    if (warp < 16) { ks = warp >> 1; rpb = (warp & 1) * 6; isU = 1; }
    else           { ks = warp - 16; rpb = 12;             isU = 0; }
    const int k0 = ks * 64;

    for (int tau = 0; tau <= TT; ++tau) {
        const int par = tau & 1;
        gridbar();

        // ---- GEMM ----
        const float* hb = isU ? &g_h0t[par][k0][lane] : &g_h1t[par][k0][lane];
        ull acc[12];
#pragma unroll
        for (int i = 0; i < 12; ++i) acc[i] = 0ull;
        gemm6(acc, sW2 + rpb * 512 + k0, hb);

#pragma unroll
        for (int i = 0; i < 6; ++i) {
            sRed[(((rpb + i) * 8 + ks) * 2 + 0) * 32 + lane] = acc[2*i];
            sRed[(((rpb + i) * 8 + ks) * 2 + 1) * 32 + lane] = acc[2*i+1];
        }
        __syncthreads();

        // ---- finisher: one output per thread (threads 0-511) ----
        if (tid < 512) {
            auto getpart = [&](int r) -> float {
                int rp = r >> 1, h = r & 1;
                float s = 0.f;
#pragma unroll
                for (int kq = 0; kq < 8; ++kq)
                    s += sRedF[((((rp * 8) + kq) * 2 + fbh) * 32 + fln) * 2 + h];
                return s;
            };

            if (fL == 0) {
                if (tau < TT) {
                    const float4* xb4 = (const float4*)(xg + ((size_t)fb * TT + tau) * INF);
                    float4 xv0 = __ldg(xb4), xv1 = __ldg(xb4 + 1);
                    float4 xv2 = __ldg(xb4 + 2), xv3 = __ldg(xb4 + 3);
                    float xa[16] = {xv0.x,xv0.y,xv0.z,xv0.w, xv1.x,xv1.y,xv1.z,xv1.w,
                                    xv2.x,xv2.y,xv2.z,xv2.w, xv3.x,xv3.y,xv3.z,xv3.w};
                    float gi[3];
#pragma unroll
                    for (int g = 0; g < 3; ++g) {
                        const float* wr = sWih0 + (fq * 3 + g) * 16;
                        float s = sB[fq * 3 + g];
#pragma unroll
                        for (int k = 0; k < 16; ++k) s = fmaf(xa[k], wr[k], s);
                        gi[g] = s;
                    }
                    float Ar = getpart(fq * 3 + 0), Az = getpart(fq * 3 + 1),
                          An = getpart(fq * 3 + 2);
                    hreg = gru_out(gi[0], gi[1], gi[2],
                                   Ar + sB[12 + fq * 3], Az + sB[13 + fq * 3],
                                   An + sB[14 + fq * 3], hreg);
                    g_h0t[par ^ 1][jb + fq][fb] = hreg;
                }
            } else {
                if (tau >= 1) {
                    float Ir = getpart(12 + fq * 3 + 0), Iz = getpart(12 + fq * 3 + 1),
                          In = getpart(12 + fq * 3 + 2);
                    float Hr = getpart(24 + fq * 3 + 0), Hz = getpart(24 + fq * 3 + 1),
                          Hn = getpart(24 + fq * 3 + 2);
                    hreg = gru_out(Ir + sB[24 + fq * 3], Iz + sB[25 + fq * 3], In + sB[26 + fq * 3],
                                   Hr + sB[36 + fq * 3], Hz + sB[37 + fq * 3], Hn + sB[38 + fq * 3],
                                   hreg);
                    g_h1t[par ^ 1][jb + fq][fb] = hreg;
                    g_h1seq[tau - 1][jb + fq][fb] = hreg;
                }
            }
        }
        // next tick's gridbar orders sRed reuse
    }
}

// ---------------- batch FC head ---------------------------------------------
__global__ void __launch_bounds__(256)
fc_kernel(const float* __restrict__ fcW, const float* __restrict__ fcb)
{
    __shared__ float sW[16 * 512];
    __shared__ float sb[16];
    const int tid = threadIdx.x;
    for (int idx = tid; idx < 16 * 512; idx += 256) sW[idx] = fcW[idx];
    if (tid < 16) sb[tid] = fcb[tid];
    __syncthreads();
    const int t = blockIdx.x, b = tid & 63, og = tid >> 6;
    float a0 = sb[og*4], a1 = sb[og*4+1], a2 = sb[og*4+2], a3 = sb[og*4+3];
    const float* w0 = sW + (og*4)*512;
    const float* w1 = sW + (og*4+1)*512;
    const float* w2 = sW + (og*4+2)*512;
    const float* w3 = sW + (og*4+3)*512;
#pragma unroll 8
    for (int k = 0; k < 512; ++k) {
        float hv = g_h1seq[t][k][b];
        a0 = fmaf(hv, w0[k], a0); a1 = fmaf(hv, w1[k], a1);
        a2 = fmaf(hv, w2[k], a2); a3 = fmaf(hv, w3[k], a3);
    }
    g_act[t][b][og*4]   = sigf(a0);
    g_act[t][b][og*4+1] = sigf(a1);
    g_act[t][b][og*4+2] = sigf(a2);
    g_act[t][b][og*4+3] = sigf(a3);
}

// ---------------- physics scan ----------------------------------------------
__global__ void __launch_bounds__(BB * JJ)
physics_kernel(const float* __restrict__ theta0, const float* __restrict__ omega0,
               float* __restrict__ out)
{
    const int tid = threadIdx.x, b = tid >> 3, j = tid & 7;
    float th = theta0[b * JJ + j], om = omega0[b * JJ + j];
    const float ma0 = -0.05f, ma1 = 0.05f, dt = 1.f / 60.f;
#pragma unroll 4
    for (int t = 0; t < TT; ++t) {
        float2 a = *(const float2*)&g_act[t][b][2 * j];
        float Km0 = fmaf(2000.f, a.x, 100.f), Km1 = fmaf(2000.f, a.y, 100.f);
        float Lm0 = fmaf(0.006f, a.x, 0.06f), Lm1 = fmaf(0.006f, a.y, 0.06f);
        float F0 = Km0 * (Lm0 - ma0 * th), F1 = Km1 * (Lm1 - ma1 * th);
        float tau = ma0 * F0 + ma1 * F1;
        float acc = (tau - 5.f * th - 0.3f * om) / 0.004f;
        om = fmaf(dt, acc, om);
        th = fmaf(dt, om, th);
        out[((size_t)b * TT + t) * JJ + j] = th;
    }
}

// ---------------- launch ----------------------------------------------------
extern "C" void kernel_launch(void* const* d_in, const int* in_sizes, int n_in,
                              void* d_out, int out_size)
{
    const float* x      = (const float*)d_in[0];
    const float* W_ih0  = (const float*)d_in[1];
    const float* W_hh0  = (const float*)d_in[2];
    const float* b_ih0  = (const float*)d_in[3];
    const float* b_hh0  = (const float*)d_in[4];
    const float* W_ih1  = (const float*)d_in[5];
    const float* W_hh1  = (const float*)d_in[6];
    const float* b_ih1  = (const float*)d_in[7];
    const float* b_hh1  = (const float*)d_in[8];
    const float* fc_W   = (const float*)d_in[9];
    const float* fc_b   = (const float*)d_in[10];
    const float* h0     = (const float*)d_in[11];
    const float* theta0 = (const float*)d_in[12];
    const float* omega0 = (const float*)d_in[13];
    float* out = (float*)d_out;

    cudaFuncSetAttribute(rnn_persistent,
                         cudaFuncAttributeMaxDynamicSharedMemorySize, SMEM_BYTES);

    rnn_persistent<<<NCTA, NTH, SMEM_BYTES>>>(
        x, W_ih0, b_ih0, W_hh0, b_hh0, W_ih1, b_ih1, W_hh1, b_hh1, h0);
    fc_kernel<<<TT, 256>>>(fc_W, fc_b);
    physics_kernel<<<1, BB * JJ>>>(theta0, omega0, out);
}

// round 12
// speedup vs baseline: 1.4023x; 1.0583x over previous
#include <cuda_runtime.h>
#include <math.h>
#include <stdint.h>

#define BB 64
#define TT 512
#define INF 16
#define HH 512
#define JJ 8
#define NCTA 128
#define NTH 768
#define JPC 4

typedef unsigned long long ull;

// ---------------- device scratch ------------------------------------------
__device__ float g_h0t[2][HH][BB];
__device__ float g_h1t[2][HH][BB];
__device__ float g_h1seq[TT][HH][BB];      // 64 MB
__device__ float g_act[TT][BB][2*JJ];
__device__ unsigned g_barcnt, g_bargen;

// ---------------- grid barrier (tid0-only fence; PTX fences are cumulative) -
__device__ __forceinline__ void gridbar()
{
    __syncthreads();
    if (threadIdx.x == 0) {
        __threadfence();     // releases ALL CTA threads' stores (ordered in via syncthreads)
        unsigned g = *((volatile unsigned*)&g_bargen);
        if (atomicAdd(&g_barcnt, 1u) == NCTA - 1) {
            *((volatile unsigned*)&g_barcnt) = 0u;
            __threadfence();
            *((volatile unsigned*)&g_bargen) = g + 1u;
        } else {
            while (*((volatile unsigned*)&g_bargen) == g) {}
        }
        __threadfence();     // acquire side
    }
    __syncthreads();
}

__device__ __forceinline__ float sigf(float x) { return 1.f / (1.f + expf(-x)); }

__device__ __forceinline__ ull dup2(float w)
{ ull d; asm("mov.b64 %0,{%1,%1};" : "=l"(d) : "f"(w)); return d; }
__device__ __forceinline__ ull fma2(ull a, ull b, ull c)
{ ull d; asm("fma.rn.f32x2 %0,%1,%2,%3;" : "=l"(d) : "l"(a), "l"(b), "l"(c)); return d; }

__device__ __forceinline__ float gru_out(float gr, float gz, float gn,
                                         float hr, float hz, float hn, float ho)
{
    float r = sigf(gr + hr);
    float z = sigf(gz + hz);
    float n = tanhf(gn + r * hn);
    return (1.f - z) * n + z * ho;
}

// ---------------- GEMM micro-kernel: 6 row-pairs x 64 k x 2 batches ---------
// Lane owns batch pair (2*lane, 2*lane+1), loaded as one float2 per k (LDG.64).
// acc[2i] = batch 2*lane, acc[2i+1] = batch 2*lane+1 (rows 2rp,2rp+1 packed).
// 16 tiles of 4 k; LDG prefetch 2 tiles deep.
__device__ __forceinline__ void gemm6(ull* acc, const ull* __restrict__ w,
                                      const float* __restrict__ hb)
{
    float2 buf[3][4];
#pragma unroll
    for (int j = 0; j < 4; ++j) {
        buf[0][j] = __ldcg((const float2*)(hb + j * 64));
        buf[1][j] = __ldcg((const float2*)(hb + (4 + j) * 64));
    }
#pragma unroll
    for (int tile = 0; tile < 16; ++tile) {
        if (tile < 14) {
            const float* nb = hb + (tile + 2) * 4 * 64;
            float2* dst = buf[(tile + 2) % 3];
#pragma unroll
            for (int j = 0; j < 4; ++j)
                dst[j] = __ldcg((const float2*)(nb + j * 64));
        }
        const float2* cb = buf[tile % 3];
#pragma unroll
        for (int s = 0; s < 2; ++s) {
            const int kk = tile * 4 + 2 * s;
            ull dA0 = dup2(cb[2*s].x),   dB0 = dup2(cb[2*s].y);
            ull dA1 = dup2(cb[2*s+1].x), dB1 = dup2(cb[2*s+1].y);
#pragma unroll
            for (int i = 0; i < 6; ++i) {
                ulonglong2 wp = *(const ulonglong2*)&w[i*512 + kk];
                acc[2*i]   = fma2(wp.x, dA0, acc[2*i]);
                acc[2*i+1] = fma2(wp.x, dB0, acc[2*i+1]);
                acc[2*i]   = fma2(wp.y, dA1, acc[2*i]);
                acc[2*i+1] = fma2(wp.y, dB1, acc[2*i+1]);
            }
        }
    }
}

// ---------------- SMEM layout (float offsets) ------------------------------
// sW2[18*512] ull | sWih0[12*16] | sB[48] | sRed[18 rp][8 kq][2 par][32] ull
#define OFF_WIH0 18432
#define OFF_B    18624
#define OFF_RED  18672
#define SMEM_FLOATS (18672 + 18432)
#define SMEM_BYTES  (SMEM_FLOATS * 4)

__global__ void __launch_bounds__(NTH, 1)
rnn_persistent(const float* __restrict__ xg,
               const float* __restrict__ Wih0, const float* __restrict__ bih0,
               const float* __restrict__ Whh0, const float* __restrict__ bhh0,
               const float* __restrict__ Wih1, const float* __restrict__ bih1,
               const float* __restrict__ Whh1, const float* __restrict__ bhh1,
               const float* __restrict__ h0in)
{
    extern __shared__ float smem[];
    ull*   sW2   = (ull*)smem;               // 9216 ull row-paired weights
    float* sW2f  = smem;
    float* sWih0 = smem + OFF_WIH0;
    float* sB    = smem + OFF_B;
    ull*   sRed  = (ull*)(smem + OFF_RED);
    float* sRedF = smem + OFF_RED;

    const int tid = threadIdx.x;
    const int jb  = blockIdx.x * JPC;

    // ---- row-paired weight slab: rows 0-11 Whh0, 12-23 Wih1, 24-35 Whh1 ----
    for (int idx = tid; idx < 18 * 512; idx += NTH) {
        int rp = idx >> 9, k = idx & 511;
#pragma unroll
        for (int h = 0; h < 2; ++h) {
            int r = 2 * rp + h;
            int m = r / 12, rr = r % 12, q = rr / 3, g = rr % 3;
            const float* M = (m == 0) ? Whh0 : ((m == 1) ? Wih1 : Whh1);
            sW2f[idx * 2 + h] = M[(g * HH + jb + q) * HH + k];
        }
    }
    for (int idx = tid; idx < 12 * 16; idx += NTH) {
        int r = idx >> 4, k = idx & 15;
        int q = r / 3, g = r % 3;
        sWih0[idx] = Wih0[(g * HH + jb + q) * INF + k];
    }
    if (tid < 12) {
        int q = tid / 3, g = tid % 3;
        int grow = g * HH + jb + q;
        sB[tid]      = bih0[grow];
        sB[12 + tid] = bhh0[grow];
        sB[24 + tid] = bih1[grow];
        sB[36 + tid] = bhh1[grow];
    }

    // ---- finisher identity (threads 0-511) ----
    const int fL = (tid >> 8) & 1;
    const int fq = (tid >> 6) & 3;
    const int fb = tid & 63;
    const int fpar = fb & 1, fhal = fb >> 1;     // batch-pair slot labels

    float hreg = 0.f;
    if (tid < 512) {
        hreg = h0in[(fL * BB + fb) * HH + jb + fq];
        if (fL == 0) {
            g_h0t[0][jb + fq][fb] = hreg;
        } else {
            g_h1t[0][jb + fq][fb] = hreg;
            g_h1t[1][jb + fq][fb] = hreg;   // h1[-1] for tick 1
        }
    }

    // ---- GEMM identity: 24 warps = 16 u-warps (8 ks x 2 rs) + 8 v-warps ----
    const int lane = tid & 31;
    const int warp = tid >> 5;
    int ks, rpb, isU;
    if (warp < 16) { ks = warp >> 1; rpb = (warp & 1) * 6; isU = 1; }
    else           { ks = warp - 16; rpb = 12;             isU = 0; }
    const int k0 = ks * 64;

    for (int tau = 0; tau <= TT; ++tau) {
        const int par = tau & 1;
        gridbar();

        // ---- GEMM ----
        const float* hb = isU ? &g_h0t[par][k0][2 * lane] : &g_h1t[par][k0][2 * lane];
        ull acc[12];
#pragma unroll
        for (int i = 0; i < 12; ++i) acc[i] = 0ull;
        gemm6(acc, sW2 + rpb * 512 + k0, hb);

#pragma unroll
        for (int i = 0; i < 6; ++i) {
            sRed[(((rpb + i) * 8 + ks) * 2 + 0) * 32 + lane] = acc[2*i];     // even batches
            sRed[(((rpb + i) * 8 + ks) * 2 + 1) * 32 + lane] = acc[2*i+1];   // odd batches
        }
        __syncthreads();

        // ---- finisher: one output per thread (threads 0-511) ----
        if (tid < 512) {
            auto getpart = [&](int r) -> float {
                int rp = r >> 1, h = r & 1;
                float s = 0.f;
#pragma unroll
                for (int kq = 0; kq < 8; ++kq)
                    s += sRedF[((((rp * 8) + kq) * 2 + fpar) * 32 + fhal) * 2 + h];
                return s;
            };

            if (fL == 0) {
                if (tau < TT) {
                    const float4* xb4 = (const float4*)(xg + ((size_t)fb * TT + tau) * INF);
                    float4 xv0 = __ldg(xb4), xv1 = __ldg(xb4 + 1);
                    float4 xv2 = __ldg(xb4 + 2), xv3 = __ldg(xb4 + 3);
                    float xa[16] = {xv0.x,xv0.y,xv0.z,xv0.w, xv1.x,xv1.y,xv1.z,xv1.w,
                                    xv2.x,xv2.y,xv2.z,xv2.w, xv3.x,xv3.y,xv3.z,xv3.w};
                    float gi[3];
#pragma unroll
                    for (int g = 0; g < 3; ++g) {
                        const float* wr = sWih0 + (fq * 3 + g) * 16;
                        float s = sB[fq * 3 + g];
#pragma unroll
                        for (int k = 0; k < 16; ++k) s = fmaf(xa[k], wr[k], s);
                        gi[g] = s;
                    }
                    float Ar = getpart(fq * 3 + 0), Az = getpart(fq * 3 + 1),
                          An = getpart(fq * 3 + 2);
                    hreg = gru_out(gi[0], gi[1], gi[2],
                                   Ar + sB[12 + fq * 3], Az + sB[13 + fq * 3],
                                   An + sB[14 + fq * 3], hreg);
                    g_h0t[par ^ 1][jb + fq][fb] = hreg;
                }
            } else {
                if (tau >= 1) {
                    float Ir = getpart(12 + fq * 3 + 0), Iz = getpart(12 + fq * 3 + 1),
                          In = getpart(12 + fq * 3 + 2);
                    float Hr = getpart(24 + fq * 3 + 0), Hz = getpart(24 + fq * 3 + 1),
                          Hn = getpart(24 + fq * 3 + 2);
                    hreg = gru_out(Ir + sB[24 + fq * 3], Iz + sB[25 + fq * 3], In + sB[26 + fq * 3],
                                   Hr + sB[36 + fq * 3], Hz + sB[37 + fq * 3], Hn + sB[38 + fq * 3],
                                   hreg);
                    g_h1t[par ^ 1][jb + fq][fb] = hreg;
                    g_h1seq[tau - 1][jb + fq][fb] = hreg;
                }
            }
        }
        // next tick's gridbar orders sRed reuse
    }
}

// ---------------- batch FC head ---------------------------------------------
__global__ void __launch_bounds__(256)
fc_kernel(const float* __restrict__ fcW, const float* __restrict__ fcb)
{
    __shared__ float sW[16 * 512];
    __shared__ float sb[16];
    const int tid = threadIdx.x;
    for (int idx = tid; idx < 16 * 512; idx += 256) sW[idx] = fcW[idx];
    if (tid < 16) sb[tid] = fcb[tid];
    __syncthreads();
    const int t = blockIdx.x, b = tid & 63, og = tid >> 6;
    float a0 = sb[og*4], a1 = sb[og*4+1], a2 = sb[og*4+2], a3 = sb[og*4+3];
    const float* w0 = sW + (og*4)*512;
    const float* w1 = sW + (og*4+1)*512;
    const float* w2 = sW + (og*4+2)*512;
    const float* w3 = sW + (og*4+3)*512;
#pragma unroll 8
    for (int k = 0; k < 512; ++k) {
        float hv = g_h1seq[t][k][b];
        a0 = fmaf(hv, w0[k], a0); a1 = fmaf(hv, w1[k], a1);
        a2 = fmaf(hv, w2[k], a2); a3 = fmaf(hv, w3[k], a3);
    }
    g_act[t][b][og*4]   = sigf(a0);
    g_act[t][b][og*4+1] = sigf(a1);
    g_act[t][b][og*4+2] = sigf(a2);
    g_act[t][b][og*4+3] = sigf(a3);
}

// ---------------- physics scan ----------------------------------------------
__global__ void __launch_bounds__(BB * JJ)
physics_kernel(const float* __restrict__ theta0, const float* __restrict__ omega0,
               float* __restrict__ out)
{
    const int tid = threadIdx.x, b = tid >> 3, j = tid & 7;
    float th = theta0[b * JJ + j], om = omega0[b * JJ + j];
    const float ma0 = -0.05f, ma1 = 0.05f, dt = 1.f / 60.f;
#pragma unroll 4
    for (int t = 0; t < TT; ++t) {
        float2 a = *(const float2*)&g_act[t][b][2 * j];
        float Km0 = fmaf(2000.f, a.x, 100.f), Km1 = fmaf(2000.f, a.y, 100.f);
        float Lm0 = fmaf(0.006f, a.x, 0.06f), Lm1 = fmaf(0.006f, a.y, 0.06f);
        float F0 = Km0 * (Lm0 - ma0 * th), F1 = Km1 * (Lm1 - ma1 * th);
        float tau = ma0 * F0 + ma1 * F1;
        float acc = (tau - 5.f * th - 0.3f * om) / 0.004f;
        om = fmaf(dt, acc, om);
        th = fmaf(dt, om, th);
        out[((size_t)b * TT + t) * JJ + j] = th;
    }
}

// ---------------- launch ----------------------------------------------------
extern "C" void kernel_launch(void* const* d_in, const int* in_sizes, int n_in,
                              void* d_out, int out_size)
{
    const float* x      = (const float*)d_in[0];
    const float* W_ih0  = (const float*)d_in[1];
    const float* W_hh0  = (const float*)d_in[2];
    const float* b_ih0  = (const float*)d_in[3];
    const float* b_hh0  = (const float*)d_in[4];
    const float* W_ih1  = (const float*)d_in[5];
    const float* W_hh1  = (const float*)d_in[6];
    const float* b_ih1  = (const float*)d_in[7];
    const float* b_hh1  = (const float*)d_in[8];
    const float* fc_W   = (const float*)d_in[9];
    const float* fc_b   = (const float*)d_in[10];
    const float* h0     = (const float*)d_in[11];
    const float* theta0 = (const float*)d_in[12];
    const float* omega0 = (const float*)d_in[13];
    float* out = (float*)d_out;

    cudaFuncSetAttribute(rnn_persistent,
                         cudaFuncAttributeMaxDynamicSharedMemorySize, SMEM_BYTES);

    rnn_persistent<<<NCTA, NTH, SMEM_BYTES>>>(
        x, W_ih0, b_ih0, W_hh0, b_hh0, W_ih1, b_ih1, W_hh1, b_hh1, h0);
    fc_kernel<<<TT, 256>>>(fc_W, fc_b);
    physics_kernel<<<1, BB * JJ>>>(theta0, omega0, out);
}

// round 14
// speedup vs baseline: 1.4693x; 1.0478x over previous
#include <cuda_runtime.h>
#include <math.h>
#include <stdint.h>

#define BB 64
#define TT 512
#define INF 16
#define HH 512
#define JJ 8
#define NCTA 128
#define NTH 768
#define JPC 4

typedef unsigned long long ull;

// ---------------- device scratch ------------------------------------------
__device__ float g_h0t[2][HH][BB];
__device__ float g_h1t[2][HH][BB];
__device__ float g_h1seq[TT][HH][BB];      // 64 MB
__device__ float g_xT[TT][INF][BB];        // 2 MB transposed input
__device__ float g_act[TT][BB][2*JJ];
__device__ unsigned g_barcnt, g_bargen;

// ---------------- grid barrier (tid0-only fence; PTX fences are cumulative) -
__device__ __forceinline__ void gridbar()
{
    __syncthreads();
    if (threadIdx.x == 0) {
        __threadfence();
        unsigned g = *((volatile unsigned*)&g_bargen);
        if (atomicAdd(&g_barcnt, 1u) == NCTA - 1) {
            *((volatile unsigned*)&g_barcnt) = 0u;
            __threadfence();
            *((volatile unsigned*)&g_bargen) = g + 1u;
        } else {
            while (*((volatile unsigned*)&g_bargen) == g) {}
        }
        __threadfence();
    }
    __syncthreads();
}

__device__ __forceinline__ float sigf(float x) { return 1.f / (1.f + expf(-x)); }

__device__ __forceinline__ ull dup2(float w)
{ ull d; asm("mov.b64 %0,{%1,%1};" : "=l"(d) : "f"(w)); return d; }
__device__ __forceinline__ ull fma2(ull a, ull b, ull c)
{ ull d; asm("fma.rn.f32x2 %0,%1,%2,%3;" : "=l"(d) : "l"(a), "l"(b), "l"(c)); return d; }

__device__ __forceinline__ float gru_out(float gr, float gz, float gn,
                                         float hr, float hz, float hn, float ho)
{
    float r = sigf(gr + hr);
    float z = sigf(gz + hz);
    float n = tanhf(gn + r * hn);
    return (1.f - z) * n + z * ho;
}

// ---------------- GEMM micro-kernel: 6 row-pairs x 64 k x 2 batches ---------
__device__ __forceinline__ void gemm6(ull* acc, const ull* __restrict__ w,
                                      const float* __restrict__ hb)
{
    float2 buf[3][4];
#pragma unroll
    for (int j = 0; j < 4; ++j) {
        buf[0][j] = __ldcg((const float2*)(hb + j * 64));
        buf[1][j] = __ldcg((const float2*)(hb + (4 + j) * 64));
    }
#pragma unroll
    for (int tile = 0; tile < 16; ++tile) {
        if (tile < 14) {
            const float* nb = hb + (tile + 2) * 4 * 64;
            float2* dst = buf[(tile + 2) % 3];
#pragma unroll
            for (int j = 0; j < 4; ++j)
                dst[j] = __ldcg((const float2*)(nb + j * 64));
        }
        const float2* cb = buf[tile % 3];
#pragma unroll
        for (int s = 0; s < 2; ++s) {
            const int kk = tile * 4 + 2 * s;
            ull dA0 = dup2(cb[2*s].x),   dB0 = dup2(cb[2*s].y);
            ull dA1 = dup2(cb[2*s+1].x), dB1 = dup2(cb[2*s+1].y);
#pragma unroll
            for (int i = 0; i < 6; ++i) {
                ulonglong2 wp = *(const ulonglong2*)&w[i*512 + kk];
                acc[2*i]   = fma2(wp.x, dA0, acc[2*i]);
                acc[2*i+1] = fma2(wp.x, dB0, acc[2*i+1]);
                acc[2*i]   = fma2(wp.y, dA1, acc[2*i]);
                acc[2*i+1] = fma2(wp.y, dB1, acc[2*i+1]);
            }
        }
    }
}

// ---------------- SMEM layout (float offsets) ------------------------------
#define OFF_WIH0 18432
#define OFF_B    18624
#define OFF_RED  18672
#define SMEM_FLOATS (18672 + 18432)
#define SMEM_BYTES  (SMEM_FLOATS * 4)

__global__ void __launch_bounds__(NTH, 1)
rnn_persistent(const float* __restrict__ Wih0, const float* __restrict__ bih0,
               const float* __restrict__ Whh0, const float* __restrict__ bhh0,
               const float* __restrict__ Wih1, const float* __restrict__ bih1,
               const float* __restrict__ Whh1, const float* __restrict__ bhh1,
               const float* __restrict__ h0in)
{
    extern __shared__ float smem[];
    ull*   sW2   = (ull*)smem;               // 9216 ull row-paired weights
    float* sW2f  = smem;
    float* sWih0 = smem + OFF_WIH0;
    float* sB    = smem + OFF_B;
    ull*   sRed  = (ull*)(smem + OFF_RED);
    float* sRedF = smem + OFF_RED;

    const int tid = threadIdx.x;
    const int jb  = blockIdx.x * JPC;

    // ---- row-paired weight slab: rows 0-11 Whh0, 12-23 Wih1, 24-35 Whh1 ----
    for (int idx = tid; idx < 18 * 512; idx += NTH) {
        int rp = idx >> 9, k = idx & 511;
#pragma unroll
        for (int h = 0; h < 2; ++h) {
            int r = 2 * rp + h;
            int m = r / 12, rr = r % 12, q = rr / 3, g = rr % 3;
            const float* M = (m == 0) ? Whh0 : ((m == 1) ? Wih1 : Whh1);
            sW2f[idx * 2 + h] = M[(g * HH + jb + q) * HH + k];
        }
    }
    for (int idx = tid; idx < 12 * 16; idx += NTH) {
        int r = idx >> 4, k = idx & 15;
        int q = r / 3, g = r % 3;
        sWih0[idx] = Wih0[(g * HH + jb + q) * INF + k];
    }
    if (tid < 12) {
        int q = tid / 3, g = tid % 3;
        int grow = g * HH + jb + q;
        sB[tid]      = bih0[grow];
        sB[12 + tid] = bhh0[grow];
        sB[24 + tid] = bih1[grow];
        sB[36 + tid] = bhh1[grow];
    }

    // ---- finisher identity (threads 0-511) ----
    const int fL = (tid >> 8) & 1;
    const int fq = (tid >> 6) & 3;
    const int fb = tid & 63;
    const int fpar = fb & 1, fhal = fb >> 1;     // batch-pair slot labels

    float hreg = 0.f;
    if (tid < 512) {
        hreg = h0in[(fL * BB + fb) * HH + jb + fq];
        if (fL == 0) {
            g_h0t[0][jb + fq][fb] = hreg;
        } else {
            g_h1t[0][jb + fq][fb] = hreg;
            g_h1t[1][jb + fq][fb] = hreg;   // h1[-1] for tick 1
        }
    }

    // ---- GEMM identity: 24 warps = 16 u-warps (8 ks x 2 rs) + 8 v-warps ----
    const int lane = tid & 31;
    const int warp = tid >> 5;
    int ks, rpb, isU;
    if (warp < 16) { ks = warp >> 1; rpb = (warp & 1) * 6; isU = 1; }
    else           { ks = warp - 16; rpb = 12;             isU = 0; }
    const int k0 = ks * 64;

    for (int tau = 0; tau <= TT; ++tau) {
        const int par = tau & 1;
        gridbar();

        // ---- GEMM ----
        const float* hb = isU ? &g_h0t[par][k0][2 * lane] : &g_h1t[par][k0][2 * lane];
        ull acc[12];
#pragma unroll
        for (int i = 0; i < 12; ++i) acc[i] = 0ull;
        gemm6(acc, sW2 + rpb * 512 + k0, hb);

#pragma unroll
        for (int i = 0; i < 6; ++i) {
            sRed[(((rpb + i) * 8 + ks) * 2 + 0) * 32 + lane] = acc[2*i];     // even batches
            sRed[(((rpb + i) * 8 + ks) * 2 + 1) * 32 + lane] = acc[2*i+1];   // odd batches
        }
        __syncthreads();

        // ---- finisher: one output per thread (threads 0-511) ----
        if (tid < 512) {
            if (fL == 0) {
                if (tau < TT) {
                    // coalesced transposed x loads — issue first, consume after LDS
                    float xa[16];
                    const float* xp = &g_xT[tau][0][fb];
#pragma unroll
                    for (int k = 0; k < 16; ++k) xa[k] = __ldg(xp + k * 64);

                    float A[3];
#pragma unroll
                    for (int g = 0; g < 3; ++g) {
                        int r = fq * 3 + g, rp = r >> 1, h = r & 1;
                        float s = 0.f;
#pragma unroll
                        for (int kq = 0; kq < 8; ++kq)
                            s += sRedF[((((rp * 8) + kq) * 2 + fpar) * 32 + fhal) * 2 + h];
                        A[g] = s;
                    }
                    float gi[3];
#pragma unroll
                    for (int g = 0; g < 3; ++g) {
                        const float* wr = sWih0 + (fq * 3 + g) * 16;
                        float s = sB[fq * 3 + g];
#pragma unroll
                        for (int k = 0; k < 16; ++k) s = fmaf(xa[k], wr[k], s);
                        gi[g] = s;
                    }
                    hreg = gru_out(gi[0], gi[1], gi[2],
                                   A[0] + sB[12 + fq * 3], A[1] + sB[13 + fq * 3],
                                   A[2] + sB[14 + fq * 3], hreg);
                    g_h0t[par ^ 1][jb + fq][fb] = hreg;
                }
            } else {
                if (tau >= 1) {
                    auto getpart = [&](int r) -> float {
                        int rp = r >> 1, h = r & 1;
                        float s = 0.f;
#pragma unroll
                        for (int kq = 0; kq < 8; ++kq)
                            s += sRedF[((((rp * 8) + kq) * 2 + fpar) * 32 + fhal) * 2 + h];
                        return s;
                    };
                    float Ir = getpart(12 + fq * 3 + 0), Iz = getpart(12 + fq * 3 + 1),
                          In = getpart(12 + fq * 3 + 2);
                    float Hr = getpart(24 + fq * 3 + 0), Hz = getpart(24 + fq * 3 + 1),
                          Hn = getpart(24 + fq * 3 + 2);
                    hreg = gru_out(Ir + sB[24 + fq * 3], Iz + sB[25 + fq * 3], In + sB[26 + fq * 3],
                                   Hr + sB[36 + fq * 3], Hz + sB[37 + fq * 3], Hn + sB[38 + fq * 3],
                                   hreg);
                    g_h1t[par ^ 1][jb + fq][fb] = hreg;
                    g_h1seq[tau - 1][jb + fq][fb] = hreg;
                }
            }
        }
        // next tick's gridbar orders sRed reuse
    }
}

// ---------------- x transpose: g_xT[t][k][b] = x[b][t][k] -------------------
__global__ void __launch_bounds__(256)
xt_kernel(const float* __restrict__ x)
{
    const int t = blockIdx.x, tid = threadIdx.x;
    for (int idx = tid; idx < INF * BB; idx += 256) {
        int k = idx >> 6, b = idx & 63;
        g_xT[t][k][b] = x[((size_t)b * TT + t) * INF + k];
    }
}

// ---------------- batch FC head (2 timesteps per CTA) -----------------------
__global__ void __launch_bounds__(256)
fc_kernel(const float* __restrict__ fcW, const float* __restrict__ fcb)
{
    __shared__ float sW[16 * 512];
    __shared__ float sb[16];
    const int tid = threadIdx.x;
    for (int idx = tid; idx < 16 * 512; idx += 256) sW[idx] = fcW[idx];
    if (tid < 16) sb[tid] = fcb[tid];
    __syncthreads();
    const int b = tid & 63, og = tid >> 6;
    const float* w0 = sW + (og*4)*512;
    const float* w1 = sW + (og*4+1)*512;
    const float* w2 = sW + (og*4+2)*512;
    const float* w3 = sW + (og*4+3)*512;
#pragma unroll
    for (int tt = 0; tt < 2; ++tt) {
        const int t = blockIdx.x * 2 + tt;
        float a0 = sb[og*4], a1 = sb[og*4+1], a2 = sb[og*4+2], a3 = sb[og*4+3];
#pragma unroll 8
        for (int k = 0; k < 512; ++k) {
            float hv = __ldcg(&g_h1seq[t][k][b]);
            a0 = fmaf(hv, w0[k], a0); a1 = fmaf(hv, w1[k], a1);
            a2 = fmaf(hv, w2[k], a2); a3 = fmaf(hv, w3[k], a3);
        }
        g_act[t][b][og*4]   = sigf(a0);
        g_act[t][b][og*4+1] = sigf(a1);
        g_act[t][b][og*4+2] = sigf(a2);
        g_act[t][b][og*4+3] = sigf(a3);
    }
}

// ---------------- physics scan (4-deep act prefetch) ------------------------
__global__ void __launch_bounds__(BB * JJ)
physics_kernel(const float* __restrict__ theta0, const float* __restrict__ omega0,
               float* __restrict__ out)
{
    const int tid = threadIdx.x, b = tid >> 3, j = tid & 7;
    float th = theta0[b * JJ + j], om = omega0[b * JJ + j];
    const float ma0 = -0.05f, ma1 = 0.05f, dt = 1.f / 60.f;

    float2 abuf[4];
#pragma unroll
    for (int p = 0; p < 4; ++p)
        abuf[p] = *(const float2*)&g_act[p][b][2 * j];

#pragma unroll 4
    for (int t = 0; t < TT; ++t) {
        float2 a = abuf[t & 3];
        if (t + 4 < TT)
            abuf[t & 3] = *(const float2*)&g_act[t + 4][b][2 * j];
        float Km0 = fmaf(2000.f, a.x, 100.f), Km1 = fmaf(2000.f, a.y, 100.f);
        float Lm0 = fmaf(0.006f, a.x, 0.06f), Lm1 = fmaf(0.006f, a.y, 0.06f);
        float F0 = Km0 * (Lm0 - ma0 * th), F1 = Km1 * (Lm1 - ma1 * th);
        float tau = ma0 * F0 + ma1 * F1;
        float acc = (tau - 5.f * th - 0.3f * om) / 0.004f;
        om = fmaf(dt, acc, om);
        th = fmaf(dt, om, th);
        out[((size_t)b * TT + t) * JJ + j] = th;
    }
}

// ---------------- launch ----------------------------------------------------
extern "C" void kernel_launch(void* const* d_in, const int* in_sizes, int n_in,
                              void* d_out, int out_size)
{
    const float* x      = (const float*)d_in[0];
    const float* W_ih0  = (const float*)d_in[1];
    const float* W_hh0  = (const float*)d_in[2];
    const float* b_ih0  = (const float*)d_in[3];
    const float* b_hh0  = (const float*)d_in[4];
    const float* W_ih1  = (const float*)d_in[5];
    const float* W_hh1  = (const float*)d_in[6];
    const float* b_ih1  = (const float*)d_in[7];
    const float* b_hh1  = (const float*)d_in[8];
    const float* fc_W   = (const float*)d_in[9];
    const float* fc_b   = (const float*)d_in[10];
    const float* h0     = (const float*)d_in[11];
    const float* theta0 = (const float*)d_in[12];
    const float* omega0 = (const float*)d_in[13];
    float* out = (float*)d_out;

    cudaFuncSetAttribute(rnn_persistent,
                         cudaFuncAttributeMaxDynamicSharedMemorySize, SMEM_BYTES);

    xt_kernel<<<TT, 256>>>(x);
    rnn_persistent<<<NCTA, NTH, SMEM_BYTES>>>(
        W_ih0, b_ih0, W_hh0, b_hh0, W_ih1, b_ih1, W_hh1, b_hh1, h0);
    fc_kernel<<<TT / 2, 256>>>(fc_W, fc_b);
    physics_kernel<<<1, BB * JJ>>>(theta0, omega0, out);
}

// round 17
// speedup vs baseline: 1.5108x; 1.0283x over previous
#include <cuda_runtime.h>
#include <math.h>
#include <stdint.h>

#define BB 64
#define TT 512
#define INF 16
#define HH 512
#define JJ 8
#define NCTA 128
#define NTH 768
#define JPC 4

typedef unsigned long long ull;

// ---------------- device scratch ------------------------------------------
__device__ float g_h0t[2][HH][BB];
__device__ float g_h1t[2][HH][BB];
__device__ float g_h1seq[TT][HH][BB];      // 64 MB
__device__ float g_xT[TT][INF][BB];        // 2 MB transposed input
__device__ float g_act[TT][BB][2*JJ];
__device__ unsigned g_slot[NCTA * 8];      // 32B-padded arrival slots
__device__ unsigned g_go;

// ---------------- slot-based grid barrier (no same-address atomics) ---------
__device__ __forceinline__ void gridbar(unsigned gen, int cid)
{
    __syncthreads();
    if (threadIdx.x == 0) {
        __threadfence();                               // release this CTA's stores
        *((volatile unsigned*)&g_slot[cid * 8]) = gen;
    }
    if (cid == 0) {
        if (threadIdx.x < 32) {
            const int lane = threadIdx.x;
            for (;;) {
                bool ok = true;
#pragma unroll
                for (int i = 0; i < 4; ++i)
                    ok &= (*((volatile unsigned*)&g_slot[(lane + 32 * i) * 8]) == gen);
                if (__all_sync(0xffffffffu, ok)) break;
            }
            if (lane == 0) {
                __threadfence();
                *((volatile unsigned*)&g_go) = gen;
            }
        }
    } else if (threadIdx.x == 0) {
        while (*((volatile unsigned*)&g_go) != gen) {}
        __threadfence();                               // acquire
    }
    __syncthreads();
}

__device__ __forceinline__ float sigf(float x) { return 1.f / (1.f + expf(-x)); }

__device__ __forceinline__ ull dup2(float w)
{ ull d; asm("mov.b64 %0,{%1,%1};" : "=l"(d) : "f"(w)); return d; }
__device__ __forceinline__ ull fma2(ull a, ull b, ull c)
{ ull d; asm("fma.rn.f32x2 %0,%1,%2,%3;" : "=l"(d) : "l"(a), "l"(b), "l"(c)); return d; }

__device__ __forceinline__ float gru_out(float gr, float gz, float gn,
                                         float hr, float hz, float hn, float ho)
{
    float r = sigf(gr + hr);
    float z = sigf(gz + hz);
    float n = tanhf(gn + r * hn);
    return (1.f - z) * n + z * ho;
}

// ---------------- GEMM micro-kernel: 6 row-pairs x 64 k x 2 batches ---------
__device__ __forceinline__ void gemm6(ull* acc, const ull* __restrict__ w,
                                      const float* __restrict__ hb)
{
    float2 buf[3][4];
#pragma unroll
    for (int j = 0; j < 4; ++j) {
        buf[0][j] = __ldcg((const float2*)(hb + j * 64));
        buf[1][j] = __ldcg((const float2*)(hb + (4 + j) * 64));
    }
#pragma unroll
    for (int tile = 0; tile < 16; ++tile) {
        if (tile < 14) {
            const float* nb = hb + (tile + 2) * 4 * 64;
            float2* dst = buf[(tile + 2) % 3];
#pragma unroll
            for (int j = 0; j < 4; ++j)
                dst[j] = __ldcg((const float2*)(nb + j * 64));
        }
        const float2* cb = buf[tile % 3];
#pragma unroll
        for (int s = 0; s < 2; ++s) {
            const int kk = tile * 4 + 2 * s;
            ull dA0 = dup2(cb[2*s].x),   dB0 = dup2(cb[2*s].y);
            ull dA1 = dup2(cb[2*s+1].x), dB1 = dup2(cb[2*s+1].y);
#pragma unroll
            for (int i = 0; i < 6; ++i) {
                ulonglong2 wp = *(const ulonglong2*)&w[i*512 + kk];
                acc[2*i]   = fma2(wp.x, dA0, acc[2*i]);
                acc[2*i+1] = fma2(wp.x, dB0, acc[2*i+1]);
                acc[2*i]   = fma2(wp.y, dA1, acc[2*i]);
                acc[2*i+1] = fma2(wp.y, dB1, acc[2*i+1]);
            }
        }
    }
}

// ---------------- SMEM layout (float offsets) ------------------------------
#define OFF_WIH0 18432
#define OFF_B    18624
#define OFF_RED  18672
#define SMEM_FLOATS (18672 + 18432)
#define SMEM_BYTES  (SMEM_FLOATS * 4)

__global__ void __launch_bounds__(NTH, 1)
rnn_persistent(const float* __restrict__ Wih0, const float* __restrict__ bih0,
               const float* __restrict__ Whh0, const float* __restrict__ bhh0,
               const float* __restrict__ Wih1, const float* __restrict__ bih1,
               const float* __restrict__ Whh1, const float* __restrict__ bhh1,
               const float* __restrict__ h0in)
{
    extern __shared__ float smem[];
    ull*   sW2   = (ull*)smem;               // 9216 ull row-paired weights
    float* sW2f  = smem;
    float* sWih0 = smem + OFF_WIH0;
    float* sB    = smem + OFF_B;
    ull*   sRed  = (ull*)(smem + OFF_RED);
    float* sRedF = smem + OFF_RED;

    const int tid = threadIdx.x;
    const int cid = blockIdx.x;
    const int jb  = cid * JPC;

    // ---- row-paired weight slab: rows 0-11 Whh0, 12-23 Wih1, 24-35 Whh1 ----
    for (int idx = tid; idx < 18 * 512; idx += NTH) {
        int rp = idx >> 9, k = idx & 511;
#pragma unroll
        for (int h = 0; h < 2; ++h) {
            int r = 2 * rp + h;
            int m = r / 12, rr = r % 12, q = rr / 3, g = rr % 3;
            const float* M = (m == 0) ? Whh0 : ((m == 1) ? Wih1 : Whh1);
            sW2f[idx * 2 + h] = M[(g * HH + jb + q) * HH + k];
        }
    }
    for (int idx = tid; idx < 12 * 16; idx += NTH) {
        int r = idx >> 4, k = idx & 15;
        int q = r / 3, g = r % 3;
        sWih0[idx] = Wih0[(g * HH + jb + q) * INF + k];
    }
    if (tid < 12) {
        int q = tid / 3, g = tid % 3;
        int grow = g * HH + jb + q;
        sB[tid]      = bih0[grow];
        sB[12 + tid] = bhh0[grow];
        sB[24 + tid] = bih1[grow];
        sB[36 + tid] = bhh1[grow];
    }

    // ---- finisher identity (threads 0-511) ----
    const int fL = (tid >> 8) & 1;
    const int fq = (tid >> 6) & 3;
    const int fb = tid & 63;
    const int fpar = fb & 1, fhal = fb >> 1;     // batch-pair slot labels

    float hreg = 0.f;
    if (tid < 512) {
        hreg = h0in[(fL * BB + fb) * HH + jb + fq];
        if (fL == 0) {
            g_h0t[0][jb + fq][fb] = hreg;
        } else {
            g_h1t[0][jb + fq][fb] = hreg;
            g_h1t[1][jb + fq][fb] = hreg;   // h1[-1] for tick 1
        }
    }

    // ---- GEMM identity: 24 warps = 16 u-warps (8 ks x 2 rs) + 8 v-warps ----
    const int lane = tid & 31;
    const int warp = tid >> 5;
    int ks, rpb, isU;
    if (warp < 16) { ks = warp >> 1; rpb = (warp & 1) * 6; isU = 1; }
    else           { ks = warp - 16; rpb = 12;             isU = 0; }
    const int k0 = ks * 64;

    for (int tau = 0; tau <= TT; ++tau) {
        const int par = tau & 1;
        gridbar((unsigned)(tau + 1), cid);

        // ---- GEMM ----
        const float* hb = isU ? &g_h0t[par][k0][2 * lane] : &g_h1t[par][k0][2 * lane];
        ull acc[12];
#pragma unroll
        for (int i = 0; i < 12; ++i) acc[i] = 0ull;
        gemm6(acc, sW2 + rpb * 512 + k0, hb);

#pragma unroll
        for (int i = 0; i < 6; ++i) {
            sRed[(((rpb + i) * 8 + ks) * 2 + 0) * 32 + lane] = acc[2*i];     // even batches
            sRed[(((rpb + i) * 8 + ks) * 2 + 1) * 32 + lane] = acc[2*i+1];   // odd batches
        }
        __syncthreads();

        // ---- finisher: one output per thread (threads 0-511) ----
        if (tid < 512) {
            if (fL == 0) {
                if (tau < TT) {
                    // coalesced transposed x loads — issue first, consume after LDS
                    float xa[16];
                    const float* xp = &g_xT[tau][0][fb];
#pragma unroll
                    for (int k = 0; k < 16; ++k) xa[k] = __ldg(xp + k * 64);

                    float A[3];
#pragma unroll
                    for (int g = 0; g < 3; ++g) {
                        int r = fq * 3 + g, rp = r >> 1, h = r & 1;
                        float s = 0.f;
#pragma unroll
                        for (int kq = 0; kq < 8; ++kq)
                            s += sRedF[((((rp * 8) + kq) * 2 + fpar) * 32 + fhal) * 2 + h];
                        A[g] = s;
                    }
                    float gi[3];
#pragma unroll
                    for (int g = 0; g < 3; ++g) {
                        const float* wr = sWih0 + (fq * 3 + g) * 16;
                        float s = sB[fq * 3 + g];
#pragma unroll
                        for (int k = 0; k < 16; ++k) s = fmaf(xa[k], wr[k], s);
                        gi[g] = s;
                    }
                    hreg = gru_out(gi[0], gi[1], gi[2],
                                   A[0] + sB[12 + fq * 3], A[1] + sB[13 + fq * 3],
                                   A[2] + sB[14 + fq * 3], hreg);
                    g_h0t[par ^ 1][jb + fq][fb] = hreg;
                }
            } else {
                if (tau >= 1) {
                    auto getpart = [&](int r) -> float {
                        int rp = r >> 1, h = r & 1;
                        float s = 0.f;
#pragma unroll
                        for (int kq = 0; kq < 8; ++kq)
                            s += sRedF[((((rp * 8) + kq) * 2 + fpar) * 32 + fhal) * 2 + h];
                        return s;
                    };
                    float Ir = getpart(12 + fq * 3 + 0), Iz = getpart(12 + fq * 3 + 1),
                          In = getpart(12 + fq * 3 + 2);
                    float Hr = getpart(24 + fq * 3 + 0), Hz = getpart(24 + fq * 3 + 1),
                          Hn = getpart(24 + fq * 3 + 2);
                    hreg = gru_out(Ir + sB[24 + fq * 3], Iz + sB[25 + fq * 3], In + sB[26 + fq * 3],
                                   Hr + sB[36 + fq * 3], Hz + sB[37 + fq * 3], Hn + sB[38 + fq * 3],
                                   hreg);
                    g_h1t[par ^ 1][jb + fq][fb] = hreg;
                    g_h1seq[tau - 1][jb + fq][fb] = hreg;
                }
            }
        }
        // next tick's gridbar orders sRed reuse
    }
}

// ---------------- x transpose: g_xT[t][k][b] = x[b][t][k] -------------------
__global__ void __launch_bounds__(256)
xt_kernel(const float* __restrict__ x)
{
    const int t = blockIdx.x, tid = threadIdx.x;
    for (int idx = tid; idx < INF * BB; idx += 256) {
        int k = idx >> 6, b = idx & 63;
        g_xT[t][k][b] = x[((size_t)b * TT + t) * INF + k];
    }
}

// ---------------- batch FC head (2 timesteps per CTA) -----------------------
__global__ void __launch_bounds__(256)
fc_kernel(const float* __restrict__ fcW, const float* __restrict__ fcb)
{
    __shared__ float sW[16 * 512];
    __shared__ float sb[16];
    const int tid = threadIdx.x;
    for (int idx = tid; idx < 16 * 512; idx += 256) sW[idx] = fcW[idx];
    if (tid < 16) sb[tid] = fcb[tid];
    __syncthreads();
    const int b = tid & 63, og = tid >> 6;
    const float* w0 = sW + (og*4)*512;
    const float* w1 = sW + (og*4+1)*512;
    const float* w2 = sW + (og*4+2)*512;
    const float* w3 = sW + (og*4+3)*512;
#pragma unroll
    for (int tt = 0; tt < 2; ++tt) {
        const int t = blockIdx.x * 2 + tt;
        float a0 = sb[og*4], a1 = sb[og*4+1], a2 = sb[og*4+2], a3 = sb[og*4+3];
#pragma unroll 8
        for (int k = 0; k < 512; ++k) {
            float hv = __ldcg(&g_h1seq[t][k][b]);
            a0 = fmaf(hv, w0[k], a0); a1 = fmaf(hv, w1[k], a1);
            a2 = fmaf(hv, w2[k], a2); a3 = fmaf(hv, w3[k], a3);
        }
        g_act[t][b][og*4]   = sigf(a0);
        g_act[t][b][og*4+1] = sigf(a1);
        g_act[t][b][og*4+2] = sigf(a2);
        g_act[t][b][og*4+3] = sigf(a3);
    }
}

// ---------------- physics scan: 16 CTAs x 32 thr, 8-deep act prefetch -------
__global__ void __launch_bounds__(32)
physics_kernel(const float* __restrict__ theta0, const float* __restrict__ omega0,
               float* __restrict__ out)
{
    const int tid = threadIdx.x;
    const int b = blockIdx.x * 4 + (tid >> 3), j = tid & 7;
    float th = theta0[b * JJ + j], om = omega0[b * JJ + j];
    const float ma0 = -0.05f, ma1 = 0.05f, dt = 1.f / 60.f;

    float2 abuf[8];
#pragma unroll
    for (int p = 0; p < 8; ++p)
        abuf[p] = *(const float2*)&g_act[p][b][2 * j];

#pragma unroll 8
    for (int t = 0; t < TT; ++t) {
        float2 a = abuf[t & 7];
        if (t + 8 < TT)
            abuf[t & 7] = *(const float2*)&g_act[t + 8][b][2 * j];
        float Km0 = fmaf(2000.f, a.x, 100.f), Km1 = fmaf(2000.f, a.y, 100.f);
        float Lm0 = fmaf(0.006f, a.x, 0.06f), Lm1 = fmaf(0.006f, a.y, 0.06f);
        float F0 = Km0 * (Lm0 - ma0 * th), F1 = Km1 * (Lm1 - ma1 * th);
        float tau = ma0 * F0 + ma1 * F1;
        float acc = (tau - 5.f * th - 0.3f * om) / 0.004f;
        om = fmaf(dt, acc, om);
        th = fmaf(dt, om, th);
        out[((size_t)b * TT + t) * JJ + j] = th;
    }
}

// ---------------- launch ----------------------------------------------------
extern "C" void kernel_launch(void* const* d_in, const int* in_sizes, int n_in,
                              void* d_out, int out_size)
{
    const float* x      = (const float*)d_in[0];
    const float* W_ih0  = (const float*)d_in[1];
    const float* W_hh0  = (const float*)d_in[2];
    const float* b_ih0  = (const float*)d_in[3];
    const float* b_hh0  = (const float*)d_in[4];
    const float* W_ih1  = (const float*)d_in[5];
    const float* W_hh1  = (const float*)d_in[6];
    const float* b_ih1  = (const float*)d_in[7];
    const float* b_hh1  = (const float*)d_in[8];
    const float* fc_W   = (const float*)d_in[9];
    const float* fc_b   = (const float*)d_in[10];
    const float* h0     = (const float*)d_in[11];
    const float* theta0 = (const float*)d_in[12];
    const float* omega0 = (const float*)d_in[13];
    float* out = (float*)d_out;

    cudaFuncSetAttribute(rnn_persistent,
                         cudaFuncAttributeMaxDynamicSharedMemorySize, SMEM_BYTES);

    xt_kernel<<<TT, 256>>>(x);
    rnn_persistent<<<NCTA, NTH, SMEM_BYTES>>>(
        W_ih0, b_ih0, W_hh0, b_hh0, W_ih1, b_ih1, W_hh1, b_hh1, h0);
    fc_kernel<<<TT / 2, 256>>>(fc_W, fc_b);
    physics_kernel<<<16, 32>>>(theta0, omega0, out);
}